// round 5
// baseline (speedup 1.0000x reference)
#include <cuda_runtime.h>
#include <cuda_bf16.h>
#include <cstdint>
#include <cstddef>

// ---------------- helpers ----------------
__device__ __forceinline__ uint32_t smem_u32(const void* p) {
    uint32_t a;
    asm("{ .reg .u64 t; cvta.to.shared.u64 t, %1; cvt.u32.u64 %0, t; }" : "=r"(a) : "l"(p));
    return a;
}
__device__ __forceinline__ void ldm_x4(uint32_t* r, uint32_t addr) {
    asm volatile("ldmatrix.sync.aligned.m8n8.x4.shared.b16 {%0,%1,%2,%3}, [%4];"
                 : "=r"(r[0]), "=r"(r[1]), "=r"(r[2]), "=r"(r[3]) : "r"(addr));
}
__device__ __forceinline__ void mma_bf16(float* c, const uint32_t* a, const uint32_t* b) {
    asm volatile("mma.sync.aligned.m16n8k16.row.col.f32.bf16.bf16.f32 "
                 "{%0,%1,%2,%3}, {%4,%5,%6,%7}, {%8,%9}, {%0,%1,%2,%3};"
                 : "+f"(c[0]), "+f"(c[1]), "+f"(c[2]), "+f"(c[3])
                 : "r"(a[0]), "r"(a[1]), "r"(a[2]), "r"(a[3]), "r"(b[0]), "r"(b[1]));
}
#define CP_ASYNC16(dst, src) \
    asm volatile("cp.async.cg.shared.global [%0], [%1], 16;" :: "r"(dst), "l"(src))
#define CP_COMMIT() asm volatile("cp.async.commit_group;" ::: "memory")

// ---------------- problem constants ----------------
#define NE 8388608            // 4*2048*1024
#define NS 16777216           // 4*2048*2048
#define WN 1048576            // 1024*1024

static constexpr int BK = 32;
static constexpr int SST = 40;                  // smem row stride (bf16): 80B, conflict-free
static constexpr uint32_t MAT_A = 128 * SST * 2;   // 10240
static constexpr uint32_t MAT_B = 256 * SST * 2;   // 20480
static constexpr uint32_t OFF_AH = 0;
static constexpr uint32_t OFF_AL = MAT_A;           // 10240
static constexpr uint32_t OFF_BH = 2 * MAT_A;       // 20480
static constexpr uint32_t OFF_BL = 2 * MAT_A + MAT_B; // 40960
static constexpr uint32_t STAGEB = 2 * MAT_A + 2 * MAT_B;  // 61440
static constexpr unsigned SMEM_BYTES = 2 * STAGEB;          // 122880

// ---------------- scratch (device globals) ----------------
__device__ __align__(256) __nv_bfloat16 g_xh[3ull * NE];
__device__ __align__(256) __nv_bfloat16 g_xl[3ull * NE];
__device__ __align__(256) __nv_bfloat16 g_wh[3ull * WN];
__device__ __align__(256) __nv_bfloat16 g_wl[3ull * WN];
__device__ __align__(256) __nv_bfloat16 g_qh[3ull * NE];
__device__ __align__(256) __nv_bfloat16 g_ql[3ull * NE];
__device__ __align__(256) __nv_bfloat16 g_vth[NE];
__device__ __align__(256) __nv_bfloat16 g_vtl[NE];
__device__ __align__(256) float         g_S[NS];
__device__ __align__(256) __nv_bfloat16 g_ph[NS];
__device__ __align__(256) __nv_bfloat16 g_pl[NS];

// ---------------- fused elementwise kernels ----------------
// all three inputs split in one launch (z selects tensor)
__global__ void split_all(const float* __restrict__ q, const float* __restrict__ k,
                          const float* __restrict__ v, __nv_bfloat16* __restrict__ hi,
                          __nv_bfloat16* __restrict__ lo) {
    const int z = blockIdx.z;
    const float* in = (z == 0) ? q : (z == 1) ? k : v;
    size_t base = (size_t)z * NE;
    size_t i = base + ((size_t)blockIdx.x * blockDim.x + threadIdx.x) * 4;
    float4 vv = *reinterpret_cast<const float4*>(in + (i - base));
    float f[4] = {vv.x, vv.y, vv.z, vv.w};
    __nv_bfloat16 h[4], l[4];
#pragma unroll
    for (int j = 0; j < 4; j++) {
        h[j] = __float2bfloat16(f[j]);
        l[j] = __float2bfloat16(f[j] - __bfloat162float(h[j]));
    }
    reinterpret_cast<__nv_bfloat162*>(hi + i)[0] = __halves2bfloat162(h[0], h[1]);
    reinterpret_cast<__nv_bfloat162*>(hi + i)[1] = __halves2bfloat162(h[2], h[3]);
    reinterpret_cast<__nv_bfloat162*>(lo + i)[0] = __halves2bfloat162(l[0], l[1]);
    reinterpret_cast<__nv_bfloat162*>(lo + i)[1] = __halves2bfloat162(l[2], l[3]);
}

// W[d][n] f32 -> Wt hi/lo [n][d] bf16, all three weights (z selects)
__global__ void wsplit_all(const float* __restrict__ Wq, const float* __restrict__ Wk,
                           const float* __restrict__ Wv, __nv_bfloat16* __restrict__ oh,
                           __nv_bfloat16* __restrict__ ol) {
    __shared__ float t[32][33];
    const int z = blockIdx.z;
    const float* W = (z == 0) ? Wq : (z == 1) ? Wk : Wv;
    size_t base = (size_t)z * WN;
    int n0 = blockIdx.x * 32, k0 = blockIdx.y * 32;
    int tx = threadIdx.x, ty = threadIdx.y;
#pragma unroll
    for (int i = 0; i < 4; i++)
        t[ty + i * 8][tx] = W[(size_t)(k0 + ty + i * 8) * 1024 + n0 + tx];
    __syncthreads();
#pragma unroll
    for (int i = 0; i < 4; i++) {
        float v = t[tx][ty + i * 8];
        __nv_bfloat16 h = __float2bfloat16(v);
        __nv_bfloat16 l = __float2bfloat16(v - __bfloat162float(h));
        size_t o = base + (size_t)(n0 + ty + i * 8) * 1024 + k0 + tx;
        oh[o] = h; ol[o] = l;
    }
}

// V hi/lo [b][s][v] -> Vt hi/lo [b][v][s]
__global__ void vtrans(const __nv_bfloat16* __restrict__ vh, const __nv_bfloat16* __restrict__ vl,
                       __nv_bfloat16* __restrict__ oh, __nv_bfloat16* __restrict__ ol) {
    __shared__ __nv_bfloat16 th[32][33], tl[32][33];
    int b = blockIdx.z;
    size_t inOff = (size_t)b * 2048 * 1024, outOff = (size_t)b * 1024 * 2048;
    int v0 = blockIdx.x * 32, s0 = blockIdx.y * 32;
    int tx = threadIdx.x, ty = threadIdx.y;
#pragma unroll
    for (int i = 0; i < 4; i++) {
        size_t idx = inOff + (size_t)(s0 + ty + i * 8) * 1024 + v0 + tx;
        th[ty + i * 8][tx] = vh[idx];
        tl[ty + i * 8][tx] = vl[idx];
    }
    __syncthreads();
#pragma unroll
    for (int i = 0; i < 4; i++) {
        size_t o = outOff + (size_t)(v0 + ty + i * 8) * 2048 + s0 + tx;
        oh[o] = th[tx][ty + i * 8];
        ol[o] = tl[tx][ty + i * 8];
    }
}

// row softmax over 2048 -> split bf16 probs
__global__ void softmax_split(const float* __restrict__ S, __nv_bfloat16* __restrict__ ph,
                              __nv_bfloat16* __restrict__ pl) {
    const int row = blockIdx.x;
    const float* x = S + (size_t)row * 2048;
    const int tid = threadIdx.x;  // 256
    float v[8];
    float mx = -1e30f;
#pragma unroll
    for (int i = 0; i < 8; i++) { v[i] = x[tid + i * 256]; mx = fmaxf(mx, v[i]); }
#pragma unroll
    for (int o = 16; o; o >>= 1) mx = fmaxf(mx, __shfl_xor_sync(0xFFFFFFFFu, mx, o));
    __shared__ float redm[8], reds[8];
    if ((tid & 31) == 0) redm[tid >> 5] = mx;
    __syncthreads();
    float m2 = redm[0];
#pragma unroll
    for (int w = 1; w < 8; w++) m2 = fmaxf(m2, redm[w]);
    float s = 0.f;
#pragma unroll
    for (int i = 0; i < 8; i++) { v[i] = __expf(v[i] - m2); s += v[i]; }
#pragma unroll
    for (int o = 16; o; o >>= 1) s += __shfl_xor_sync(0xFFFFFFFFu, s, o);
    if ((tid & 31) == 0) reds[tid >> 5] = s;
    __syncthreads();
    float st = 0.f;
#pragma unroll
    for (int w = 0; w < 8; w++) st += reds[w];
    float inv = 1.f / st;
#pragma unroll
    for (int i = 0; i < 8; i++) {
        float p = v[i] * inv;
        __nv_bfloat16 h = __float2bfloat16(p);
        __nv_bfloat16 l = __float2bfloat16(p - __bfloat162float(h));
        size_t o = (size_t)row * 2048 + tid + i * 256;
        ph[o] = h; pl[o] = l;
    }
}

// ---------------- HMMA split-bf16 GEMM: C[128x256] per CTA ----------------
// A row-major [M][K] (lda=K), B K-major [N][K] (ldb=K). bf16x3: AhBh+AhBl+AlBh.
// 8 warps, 2x4 grid, 64x64 warp tile. MODE 0: split(val+bias) ; MODE 1: val*scale.
template <int MODE>
__global__ void __launch_bounds__(256, 1)
gemm_bf16x3(const __nv_bfloat16* __restrict__ Ah, const __nv_bfloat16* __restrict__ Al,
            const __nv_bfloat16* __restrict__ Bh, const __nv_bfloat16* __restrict__ Bl,
            int lda, int ldb, int ldc, int K,
            size_t aBatch, size_t bBatch, size_t cBatch,
            const float* __restrict__ bias, float scale,
            float* __restrict__ outF, __nv_bfloat16* __restrict__ outH,
            __nv_bfloat16* __restrict__ outL) {
    extern __shared__ char sm[];
    const uint32_t sbase = smem_u32(sm);
    const int tid = threadIdx.x;
    const int lane = tid & 31, wid = tid >> 5;
    const int wm = wid >> 2, wn = wid & 3;  // 2 x 4 warp grid, 64x64 tiles
    const int z = blockIdx.z;
    Ah += (size_t)z * aBatch; Al += (size_t)z * aBatch;
    Bh += (size_t)z * bBatch; Bl += (size_t)z * bBatch;
    if (MODE == 0) { outH += (size_t)z * cBatch; outL += (size_t)z * cBatch; }
    else           { outF += (size_t)z * cBatch; }

    const int mBase = blockIdx.y * 128;
    const int nBase = blockIdx.x * 256;
    const int KT = K / BK;

    auto load_mat = [&](const __nv_bfloat16* g, int ld, int rb, uint32_t dstOff, int iters) {
#pragma unroll
        for (int i = 0; i < iters; i++) {
            int idx = tid + i * 256;
            int r = idx >> 2, c = idx & 3;
            uint32_t daddr = dstOff + (uint32_t)(r * SST + c * 8) * 2;
            const void* gp = g + (size_t)(rb + r) * ld + c * 8;
            CP_ASYNC16(daddr, gp);
        }
    };
    auto issue_load = [&](int kb, int stage) {
        const int kOff = kb * BK;
        const uint32_t sb = sbase + stage * STAGEB;
        load_mat(Ah + kOff, lda, mBase, sb + OFF_AH, 2);
        load_mat(Al + kOff, lda, mBase, sb + OFF_AL, 2);
        load_mat(Bh + kOff, ldb, nBase, sb + OFF_BH, 4);
        load_mat(Bl + kOff, ldb, nBase, sb + OFF_BL, 4);
        CP_COMMIT();
    };

    float acc[4][8][4];
#pragma unroll
    for (int i = 0; i < 4; i++)
#pragma unroll
        for (int j = 0; j < 8; j++)
#pragma unroll
            for (int e = 0; e < 4; e++) acc[i][j][e] = 0.f;

    issue_load(0, 0);

    for (int kb = 0; kb < KT; kb++) {
        if (kb + 1 < KT) {
            issue_load(kb + 1, (kb + 1) & 1);
            asm volatile("cp.async.wait_group 1;" ::: "memory");
        } else {
            asm volatile("cp.async.wait_group 0;" ::: "memory");
        }
        __syncthreads();

        const uint32_t sb = sbase + (kb & 1) * STAGEB;
#pragma unroll
        for (int ks = 0; ks < 2; ks++) {
            // A fragments hi & lo, 4 m-tiles (64 rows)
            uint32_t ah[4][4], al[4][4];
            const int rowA = wm * 64 + (lane & 15);
            const int colA = ks * 16 + (lane >> 4) * 8;
#pragma unroll
            for (int mt = 0; mt < 4; mt++) {
                uint32_t off = (uint32_t)((rowA + mt * 16) * SST + colA) * 2;
                ldm_x4(ah[mt], sb + OFF_AH + off);
                ldm_x4(al[mt], sb + OFF_AL + off);
            }
            // B: 8 n-tiles in 4 pairs; per pair load hi & lo, then product-major MMAs
            const int rB = wn * 64 + ((lane >> 4) << 3) + (lane & 7);
            const int cB = ks * 16 + (((lane >> 3) & 1) << 3);
#pragma unroll
            for (int bp = 0; bp < 4; bp++) {
                uint32_t off = (uint32_t)((rB + bp * 16) * SST + cB) * 2;
                uint32_t th[4], tl[4];
                ldm_x4(th, sb + OFF_BH + off);
                ldm_x4(tl, sb + OFF_BL + off);
#pragma unroll
                for (int mt = 0; mt < 4; mt++) {
                    mma_bf16(acc[mt][bp * 2 + 0], ah[mt], th + 0);
                    mma_bf16(acc[mt][bp * 2 + 1], ah[mt], th + 2);
                }
#pragma unroll
                for (int mt = 0; mt < 4; mt++) {
                    mma_bf16(acc[mt][bp * 2 + 0], ah[mt], tl + 0);
                    mma_bf16(acc[mt][bp * 2 + 1], ah[mt], tl + 2);
                }
#pragma unroll
                for (int mt = 0; mt < 4; mt++) {
                    mma_bf16(acc[mt][bp * 2 + 0], al[mt], th + 0);
                    mma_bf16(acc[mt][bp * 2 + 1], al[mt], th + 2);
                }
            }
        }
        __syncthreads();
    }

    // epilogue
    const int g = lane >> 2, tq = lane & 3;
#pragma unroll
    for (int mt = 0; mt < 4; mt++) {
        const int row = mBase + wm * 64 + mt * 16 + g;
#pragma unroll
        for (int nt = 0; nt < 8; nt++) {
            const int col = nBase + wn * 64 + nt * 8 + tq * 2;
            const float* c = acc[mt][nt];
            if (MODE == 0) {
                float b0 = bias[col], b1 = bias[col + 1];
#pragma unroll
                for (int half = 0; half < 2; half++) {
                    int rr = row + half * 8;
                    float v0 = c[half * 2 + 0] + b0;
                    float v1 = c[half * 2 + 1] + b1;
                    __nv_bfloat16 h0 = __float2bfloat16(v0);
                    __nv_bfloat16 h1 = __float2bfloat16(v1);
                    __nv_bfloat16 l0 = __float2bfloat16(v0 - __bfloat162float(h0));
                    __nv_bfloat16 l1 = __float2bfloat16(v1 - __bfloat162float(h1));
                    size_t o = (size_t)rr * ldc + col;
                    *reinterpret_cast<__nv_bfloat162*>(outH + o) = __halves2bfloat162(h0, h1);
                    *reinterpret_cast<__nv_bfloat162*>(outL + o) = __halves2bfloat162(l0, l1);
                }
            } else {
                float2 v0 = {c[0] * scale, c[1] * scale};
                float2 v1 = {c[2] * scale, c[3] * scale};
                *reinterpret_cast<float2*>(outF + (size_t)row * ldc + col) = v0;
                *reinterpret_cast<float2*>(outF + (size_t)(row + 8) * ldc + col) = v1;
            }
        }
    }
}

// ---------------- launch ----------------
extern "C" void kernel_launch(void* const* d_in, const int* in_sizes, int n_in,
                              void* d_out, int out_size) {
    const float* q_in = (const float*)d_in[0];
    const float* k_in = (const float*)d_in[1];
    const float* v_in = (const float*)d_in[2];
    const float* Wq   = (const float*)d_in[3];
    const float* bq   = (const float*)d_in[4];
    const float* Wk   = (const float*)d_in[5];
    const float* bk   = (const float*)d_in[6];
    const float* Wv   = (const float*)d_in[7];
    const float* bv   = (const float*)d_in[8];
    float* out = (float*)d_out;

    cudaFuncSetAttribute(gemm_bf16x3<0>, cudaFuncAttributeMaxDynamicSharedMemorySize, SMEM_BYTES);
    cudaFuncSetAttribute(gemm_bf16x3<1>, cudaFuncAttributeMaxDynamicSharedMemorySize, SMEM_BYTES);

    void* p;
    cudaGetSymbolAddress(&p, g_xh);  __nv_bfloat16* xh = (__nv_bfloat16*)p;
    cudaGetSymbolAddress(&p, g_xl);  __nv_bfloat16* xl = (__nv_bfloat16*)p;
    cudaGetSymbolAddress(&p, g_wh);  __nv_bfloat16* wh = (__nv_bfloat16*)p;
    cudaGetSymbolAddress(&p, g_wl);  __nv_bfloat16* wl = (__nv_bfloat16*)p;
    cudaGetSymbolAddress(&p, g_qh);  __nv_bfloat16* qh = (__nv_bfloat16*)p;
    cudaGetSymbolAddress(&p, g_ql);  __nv_bfloat16* ql = (__nv_bfloat16*)p;
    cudaGetSymbolAddress(&p, g_vth); __nv_bfloat16* vth = (__nv_bfloat16*)p;
    cudaGetSymbolAddress(&p, g_vtl); __nv_bfloat16* vtl = (__nv_bfloat16*)p;
    cudaGetSymbolAddress(&p, g_S);   float* Sb = (float*)p;
    cudaGetSymbolAddress(&p, g_ph);  __nv_bfloat16* ph = (__nv_bfloat16*)p;
    cudaGetSymbolAddress(&p, g_pl);  __nv_bfloat16* pl = (__nv_bfloat16*)p;

    const float* bs[3] = {bq, bk, bv};

    // launches 0,1: fused prep
    split_all<<<dim3(8192, 1, 3), 256>>>(q_in, k_in, v_in, xh, xl);
    wsplit_all<<<dim3(32, 32, 3), dim3(32, 8)>>>(Wq, Wk, Wv, wh, wl);
    // launches 2-4: projections [8192,1024] = X x W + b -> split bf16
    for (int i = 0; i < 3; i++) {
        gemm_bf16x3<0><<<dim3(4, 64, 1), 256, SMEM_BYTES>>>(
            xh + (size_t)i * NE, xl + (size_t)i * NE, wh + (size_t)i * WN, wl + (size_t)i * WN,
            1024, 1024, 1024, 1024, 0, 0, 0,
            bs[i], 0.f, nullptr, qh + (size_t)i * NE, ql + (size_t)i * NE);
    }
    // launch 5 (ncu target): scores S[2048,2048] = Q x K^T, scale 1/32
    gemm_bf16x3<1><<<dim3(8, 16, 4), 256, SMEM_BYTES>>>(
        qh, ql, qh + NE, ql + NE,
        1024, 1024, 2048, 1024,
        (size_t)2048 * 1024, (size_t)2048 * 1024, (size_t)2048 * 2048,
        nullptr, 0.03125f, Sb, nullptr, nullptr);
    softmax_split<<<8192, 256>>>(Sb, ph, pl);
    vtrans<<<dim3(32, 64, 4), dim3(32, 8)>>>(qh + 2ull * NE, ql + 2ull * NE, vth, vtl);
    // O = P x V  (B operand = V^T rows, K-major over s)
    gemm_bf16x3<1><<<dim3(4, 16, 4), 256, SMEM_BYTES>>>(
        ph, pl, vth, vtl,
        2048, 2048, 1024, 2048,
        (size_t)2048 * 2048, (size_t)1024 * 2048, (size_t)2048 * 1024,
        nullptr, 1.0f, out, nullptr, nullptr);
}

// round 6
// speedup vs baseline: 1.1357x; 1.1357x over previous
#include <cuda_runtime.h>
#include <cuda_bf16.h>
#include <cstdint>
#include <cstddef>

// ---------------- helpers ----------------
__device__ __forceinline__ uint32_t smem_u32(const void* p) {
    uint32_t a;
    asm("{ .reg .u64 t; cvta.to.shared.u64 t, %1; cvt.u32.u64 %0, t; }" : "=r"(a) : "l"(p));
    return a;
}
__device__ __forceinline__ void ldm_x4(uint32_t* r, uint32_t addr) {
    asm volatile("ldmatrix.sync.aligned.m8n8.x4.shared.b16 {%0,%1,%2,%3}, [%4];"
                 : "=r"(r[0]), "=r"(r[1]), "=r"(r[2]), "=r"(r[3]) : "r"(addr));
}
__device__ __forceinline__ void mma_bf16(float* c, const uint32_t* a, const uint32_t* b) {
    asm volatile("mma.sync.aligned.m16n8k16.row.col.f32.bf16.bf16.f32 "
                 "{%0,%1,%2,%3}, {%4,%5,%6,%7}, {%8,%9}, {%0,%1,%2,%3};"
                 : "+f"(c[0]), "+f"(c[1]), "+f"(c[2]), "+f"(c[3])
                 : "r"(a[0]), "r"(a[1]), "r"(a[2]), "r"(a[3]), "r"(b[0]), "r"(b[1]));
}
#define CP_ASYNC16(dst, src) \
    asm volatile("cp.async.cg.shared.global [%0], [%1], 16;" :: "r"(dst), "l"(src))
#define CP_COMMIT() asm volatile("cp.async.commit_group;" ::: "memory")

// ---------------- problem constants ----------------
#define NE 8388608            // 4*2048*1024
#define NS 16777216           // 4*2048*2048
#define WN 1048576            // 1024*1024

static constexpr int BK = 32;
static constexpr int SST = 40;                      // smem row stride (bf16): 80B
static constexpr uint32_t MATB = 128 * SST * 2;     // 10240 per 128x32 tile
static constexpr uint32_t OFF_AH = 0;
static constexpr uint32_t OFF_AL = MATB;
static constexpr uint32_t OFF_BH = 2 * MATB;
static constexpr uint32_t OFF_BL = 3 * MATB;
static constexpr uint32_t STAGEB = 4 * MATB;        // 40960
static constexpr unsigned SMEM_BYTES = 2 * STAGEB;  // 81920

// ---------------- scratch (device globals) ----------------
__device__ __align__(256) __nv_bfloat16 g_xh[3ull * NE];
__device__ __align__(256) __nv_bfloat16 g_xl[3ull * NE];
__device__ __align__(256) __nv_bfloat16 g_wh[3ull * WN];
__device__ __align__(256) __nv_bfloat16 g_wl[3ull * WN];
__device__ __align__(256) __nv_bfloat16 g_qh[3ull * NE];
__device__ __align__(256) __nv_bfloat16 g_ql[3ull * NE];
__device__ __align__(256) __nv_bfloat16 g_vth[NE];
__device__ __align__(256) __nv_bfloat16 g_vtl[NE];
__device__ __align__(256) float         g_S[NS];
__device__ __align__(256) __nv_bfloat16 g_ph[NS];
__device__ __align__(256) __nv_bfloat16 g_pl[NS];
__device__ __align__(256) float         g_bias[3072];

// ---------------- fused elementwise kernels ----------------
__global__ void split_all(const float* __restrict__ q, const float* __restrict__ k,
                          const float* __restrict__ v, __nv_bfloat16* __restrict__ hi,
                          __nv_bfloat16* __restrict__ lo) {
    const int z = blockIdx.z;
    const float* in = (z == 0) ? q : (z == 1) ? k : v;
    size_t base = (size_t)z * NE;
    size_t li = ((size_t)blockIdx.x * blockDim.x + threadIdx.x) * 4;
    size_t i = base + li;
    float4 vv = *reinterpret_cast<const float4*>(in + li);
    float f[4] = {vv.x, vv.y, vv.z, vv.w};
    __nv_bfloat16 h[4], l[4];
#pragma unroll
    for (int j = 0; j < 4; j++) {
        h[j] = __float2bfloat16(f[j]);
        l[j] = __float2bfloat16(f[j] - __bfloat162float(h[j]));
    }
    reinterpret_cast<__nv_bfloat162*>(hi + i)[0] = __halves2bfloat162(h[0], h[1]);
    reinterpret_cast<__nv_bfloat162*>(hi + i)[1] = __halves2bfloat162(h[2], h[3]);
    reinterpret_cast<__nv_bfloat162*>(lo + i)[0] = __halves2bfloat162(l[0], l[1]);
    reinterpret_cast<__nv_bfloat162*>(lo + i)[1] = __halves2bfloat162(l[2], l[3]);
}

// W[d][n] f32 -> Wt hi/lo [n][d] bf16, all three weights (z selects)
__global__ void wsplit_all(const float* __restrict__ Wq, const float* __restrict__ Wk,
                           const float* __restrict__ Wv, __nv_bfloat16* __restrict__ oh,
                           __nv_bfloat16* __restrict__ ol) {
    __shared__ float t[32][33];
    const int z = blockIdx.z;
    const float* W = (z == 0) ? Wq : (z == 1) ? Wk : Wv;
    size_t base = (size_t)z * WN;
    int n0 = blockIdx.x * 32, k0 = blockIdx.y * 32;
    int tx = threadIdx.x, ty = threadIdx.y;
#pragma unroll
    for (int i = 0; i < 4; i++)
        t[ty + i * 8][tx] = W[(size_t)(k0 + ty + i * 8) * 1024 + n0 + tx];
    __syncthreads();
#pragma unroll
    for (int i = 0; i < 4; i++) {
        float v = t[tx][ty + i * 8];
        __nv_bfloat16 h = __float2bfloat16(v);
        __nv_bfloat16 l = __float2bfloat16(v - __bfloat162float(h));
        size_t o = base + (size_t)(n0 + ty + i * 8) * 1024 + k0 + tx;
        oh[o] = h; ol[o] = l;
    }
}

// V hi/lo [b][s][v] -> Vt hi/lo [b][v][s]
__global__ void vtrans(const __nv_bfloat16* __restrict__ vh, const __nv_bfloat16* __restrict__ vl,
                       __nv_bfloat16* __restrict__ oh, __nv_bfloat16* __restrict__ ol) {
    __shared__ __nv_bfloat16 th[32][33], tl[32][33];
    int b = blockIdx.z;
    size_t inOff = (size_t)b * 2048 * 1024, outOff = (size_t)b * 1024 * 2048;
    int v0 = blockIdx.x * 32, s0 = blockIdx.y * 32;
    int tx = threadIdx.x, ty = threadIdx.y;
#pragma unroll
    for (int i = 0; i < 4; i++) {
        size_t idx = inOff + (size_t)(s0 + ty + i * 8) * 1024 + v0 + tx;
        th[ty + i * 8][tx] = vh[idx];
        tl[ty + i * 8][tx] = vl[idx];
    }
    __syncthreads();
#pragma unroll
    for (int i = 0; i < 4; i++) {
        size_t o = outOff + (size_t)(v0 + ty + i * 8) * 2048 + s0 + tx;
        oh[o] = th[tx][ty + i * 8];
        ol[o] = tl[tx][ty + i * 8];
    }
}

// row softmax over 2048 -> split bf16 probs
__global__ void softmax_split(const float* __restrict__ S, __nv_bfloat16* __restrict__ ph,
                              __nv_bfloat16* __restrict__ pl) {
    const int row = blockIdx.x;
    const float* x = S + (size_t)row * 2048;
    const int tid = threadIdx.x;  // 256
    float v[8];
    float mx = -1e30f;
#pragma unroll
    for (int i = 0; i < 8; i++) { v[i] = x[tid + i * 256]; mx = fmaxf(mx, v[i]); }
#pragma unroll
    for (int o = 16; o; o >>= 1) mx = fmaxf(mx, __shfl_xor_sync(0xFFFFFFFFu, mx, o));
    __shared__ float redm[8], reds[8];
    if ((tid & 31) == 0) redm[tid >> 5] = mx;
    __syncthreads();
    float m2 = redm[0];
#pragma unroll
    for (int w = 1; w < 8; w++) m2 = fmaxf(m2, redm[w]);
    float s = 0.f;
#pragma unroll
    for (int i = 0; i < 8; i++) { v[i] = __expf(v[i] - m2); s += v[i]; }
#pragma unroll
    for (int o = 16; o; o >>= 1) s += __shfl_xor_sync(0xFFFFFFFFu, s, o);
    if ((tid & 31) == 0) reds[tid >> 5] = s;
    __syncthreads();
    float st = 0.f;
#pragma unroll
    for (int w = 0; w < 8; w++) st += reds[w];
    float inv = 1.f / st;
#pragma unroll
    for (int i = 0; i < 8; i++) {
        float p = v[i] * inv;
        __nv_bfloat16 h = __float2bfloat16(p);
        __nv_bfloat16 l = __float2bfloat16(p - __bfloat162float(h));
        size_t o = (size_t)row * 2048 + tid + i * 256;
        ph[o] = h; pl[o] = l;
    }
}

// ---------------- HMMA split-bf16 GEMM: C[128x128] per CTA, 4 warps ----------------
// Warp tile 64x64, 2x2 warp grid, 128 threads, 2 CTAs/SM.
// A row-major [M][K] (lda=K), B K-major [N][K] (ldb=K). bf16x3: AhBh+AhBl+AlBh.
// MODE 0: split(val+bias[z*biasStride+col]) ; MODE 1: val*scale -> fp32.
template <int MODE>
__global__ void __launch_bounds__(128, 2)
gemm_bf16x3(const __nv_bfloat16* __restrict__ Ah, const __nv_bfloat16* __restrict__ Al,
            const __nv_bfloat16* __restrict__ Bh, const __nv_bfloat16* __restrict__ Bl,
            int lda, int ldb, int ldc, int K,
            size_t aBatch, size_t bBatch, size_t cBatch,
            const float* __restrict__ bias, int biasStride, float scale,
            float* __restrict__ outF, __nv_bfloat16* __restrict__ outH,
            __nv_bfloat16* __restrict__ outL) {
    extern __shared__ char sm[];
    const uint32_t sbase = smem_u32(sm);
    const int tid = threadIdx.x;
    const int lane = tid & 31, wid = tid >> 5;
    const int wm = wid >> 1, wn = wid & 1;  // 2x2 warp grid, 64x64 tiles
    const int z = blockIdx.z;
    Ah += (size_t)z * aBatch; Al += (size_t)z * aBatch;
    Bh += (size_t)z * bBatch; Bl += (size_t)z * bBatch;
    if (MODE == 0) { outH += (size_t)z * cBatch; outL += (size_t)z * cBatch; bias += (size_t)z * biasStride; }
    else           { outF += (size_t)z * cBatch; }

    const int mBase = blockIdx.y * 128;
    const int nBase = blockIdx.x * 128;
    const int KT = K / BK;

    auto load_mat = [&](const __nv_bfloat16* g, int ld, int rb, uint32_t dstOff) {
#pragma unroll
        for (int i = 0; i < 4; i++) {
            int idx = tid + i * 128;
            int r = idx >> 2, c = idx & 3;
            uint32_t daddr = dstOff + (uint32_t)(r * SST + c * 8) * 2;
            const void* gp = g + (size_t)(rb + r) * ld + c * 8;
            CP_ASYNC16(daddr, gp);
        }
    };
    auto issue_load = [&](int kb, int stage) {
        const int kOff = kb * BK;
        const uint32_t sb = sbase + stage * STAGEB;
        load_mat(Ah + kOff, lda, mBase, sb + OFF_AH);
        load_mat(Al + kOff, lda, mBase, sb + OFF_AL);
        load_mat(Bh + kOff, ldb, nBase, sb + OFF_BH);
        load_mat(Bl + kOff, ldb, nBase, sb + OFF_BL);
        CP_COMMIT();
    };

    float acc[4][8][4];
#pragma unroll
    for (int i = 0; i < 4; i++)
#pragma unroll
        for (int j = 0; j < 8; j++)
#pragma unroll
            for (int e = 0; e < 4; e++) acc[i][j][e] = 0.f;

    issue_load(0, 0);

    for (int kb = 0; kb < KT; kb++) {
        if (kb + 1 < KT) {
            issue_load(kb + 1, (kb + 1) & 1);
            asm volatile("cp.async.wait_group 1;" ::: "memory");
        } else {
            asm volatile("cp.async.wait_group 0;" ::: "memory");
        }
        __syncthreads();

        const uint32_t sb = sbase + (kb & 1) * STAGEB;
#pragma unroll
        for (int ks = 0; ks < 2; ks++) {
            // A fragments hi & lo, 4 m-tiles (64 rows)
            uint32_t ah[4][4], al[4][4];
            const int rowA = wm * 64 + (lane & 15);
            const int colA = ks * 16 + (lane >> 4) * 8;
#pragma unroll
            for (int mt = 0; mt < 4; mt++) {
                uint32_t off = (uint32_t)((rowA + mt * 16) * SST + colA) * 2;
                ldm_x4(ah[mt], sb + OFF_AH + off);
                ldm_x4(al[mt], sb + OFF_AL + off);
            }
            // B: 8 n-tiles in 4 pairs; per pair load hi & lo, product-major MMAs
            const int rB = wn * 64 + ((lane >> 4) << 3) + (lane & 7);
            const int cB = ks * 16 + (((lane >> 3) & 1) << 3);
#pragma unroll
            for (int bp = 0; bp < 4; bp++) {
                uint32_t off = (uint32_t)((rB + bp * 16) * SST + cB) * 2;
                uint32_t th[4], tl[4];
                ldm_x4(th, sb + OFF_BH + off);
                ldm_x4(tl, sb + OFF_BL + off);
#pragma unroll
                for (int mt = 0; mt < 4; mt++) {
                    mma_bf16(acc[mt][bp * 2 + 0], ah[mt], th + 0);
                    mma_bf16(acc[mt][bp * 2 + 1], ah[mt], th + 2);
                }
#pragma unroll
                for (int mt = 0; mt < 4; mt++) {
                    mma_bf16(acc[mt][bp * 2 + 0], ah[mt], tl + 0);
                    mma_bf16(acc[mt][bp * 2 + 1], ah[mt], tl + 2);
                }
#pragma unroll
                for (int mt = 0; mt < 4; mt++) {
                    mma_bf16(acc[mt][bp * 2 + 0], al[mt], th + 0);
                    mma_bf16(acc[mt][bp * 2 + 1], al[mt], th + 2);
                }
            }
        }
        __syncthreads();
    }

    // epilogue
    const int g = lane >> 2, tq = lane & 3;
#pragma unroll
    for (int mt = 0; mt < 4; mt++) {
        const int row = mBase + wm * 64 + mt * 16 + g;
#pragma unroll
        for (int nt = 0; nt < 8; nt++) {
            const int col = nBase + wn * 64 + nt * 8 + tq * 2;
            const float* c = acc[mt][nt];
            if (MODE == 0) {
                float b0 = bias[col], b1 = bias[col + 1];
#pragma unroll
                for (int half = 0; half < 2; half++) {
                    int rr = row + half * 8;
                    float v0 = c[half * 2 + 0] + b0;
                    float v1 = c[half * 2 + 1] + b1;
                    __nv_bfloat16 h0 = __float2bfloat16(v0);
                    __nv_bfloat16 h1 = __float2bfloat16(v1);
                    __nv_bfloat16 l0 = __float2bfloat16(v0 - __bfloat162float(h0));
                    __nv_bfloat16 l1 = __float2bfloat16(v1 - __bfloat162float(h1));
                    size_t o = (size_t)rr * ldc + col;
                    *reinterpret_cast<__nv_bfloat162*>(outH + o) = __halves2bfloat162(h0, h1);
                    *reinterpret_cast<__nv_bfloat162*>(outL + o) = __halves2bfloat162(l0, l1);
                }
            } else {
                float2 v0 = {c[0] * scale, c[1] * scale};
                float2 v1 = {c[2] * scale, c[3] * scale};
                *reinterpret_cast<float2*>(outF + (size_t)row * ldc + col) = v0;
                *reinterpret_cast<float2*>(outF + (size_t)(row + 8) * ldc + col) = v1;
            }
        }
    }
}

// ---------------- launch ----------------
extern "C" void kernel_launch(void* const* d_in, const int* in_sizes, int n_in,
                              void* d_out, int out_size) {
    const float* q_in = (const float*)d_in[0];
    const float* k_in = (const float*)d_in[1];
    const float* v_in = (const float*)d_in[2];
    const float* Wq   = (const float*)d_in[3];
    const float* bq   = (const float*)d_in[4];
    const float* Wk   = (const float*)d_in[5];
    const float* bk   = (const float*)d_in[6];
    const float* Wv   = (const float*)d_in[7];
    const float* bv   = (const float*)d_in[8];
    float* out = (float*)d_out;

    cudaFuncSetAttribute(gemm_bf16x3<0>, cudaFuncAttributeMaxDynamicSharedMemorySize, SMEM_BYTES);
    cudaFuncSetAttribute(gemm_bf16x3<1>, cudaFuncAttributeMaxDynamicSharedMemorySize, SMEM_BYTES);

    void* p;
    cudaGetSymbolAddress(&p, g_xh);  __nv_bfloat16* xh = (__nv_bfloat16*)p;
    cudaGetSymbolAddress(&p, g_xl);  __nv_bfloat16* xl = (__nv_bfloat16*)p;
    cudaGetSymbolAddress(&p, g_wh);  __nv_bfloat16* wh = (__nv_bfloat16*)p;
    cudaGetSymbolAddress(&p, g_wl);  __nv_bfloat16* wl = (__nv_bfloat16*)p;
    cudaGetSymbolAddress(&p, g_qh);  __nv_bfloat16* qh = (__nv_bfloat16*)p;
    cudaGetSymbolAddress(&p, g_ql);  __nv_bfloat16* ql = (__nv_bfloat16*)p;
    cudaGetSymbolAddress(&p, g_vth); __nv_bfloat16* vth = (__nv_bfloat16*)p;
    cudaGetSymbolAddress(&p, g_vtl); __nv_bfloat16* vtl = (__nv_bfloat16*)p;
    cudaGetSymbolAddress(&p, g_S);   float* Sb = (float*)p;
    cudaGetSymbolAddress(&p, g_ph);  __nv_bfloat16* ph = (__nv_bfloat16*)p;
    cudaGetSymbolAddress(&p, g_pl);  __nv_bfloat16* pl = (__nv_bfloat16*)p;
    cudaGetSymbolAddress(&p, g_bias); float* bias = (float*)p;

    // pack biases into one array (D2D, graph-capturable)
    cudaMemcpyAsync(bias,        bq, 1024 * sizeof(float), cudaMemcpyDeviceToDevice);
    cudaMemcpyAsync(bias + 1024, bk, 1024 * sizeof(float), cudaMemcpyDeviceToDevice);
    cudaMemcpyAsync(bias + 2048, bv, 1024 * sizeof(float), cudaMemcpyDeviceToDevice);

    // fused prep
    split_all<<<dim3(8192, 1, 3), 256>>>(q_in, k_in, v_in, xh, xl);
    wsplit_all<<<dim3(32, 32, 3), dim3(32, 8)>>>(Wq, Wk, Wv, wh, wl);
    // all 3 projections in ONE launch (z = q/k/v): [8192,1024] = X x W + b -> split bf16
    gemm_bf16x3<0><<<dim3(8, 64, 3), 128, SMEM_BYTES>>>(
        xh, xl, wh, wl,
        1024, 1024, 1024, 1024,
        (size_t)NE, (size_t)WN, (size_t)NE,
        bias, 1024, 0.f, nullptr, qh, ql);
    // transpose V (split) right after projections
    vtrans<<<dim3(32, 64, 4), dim3(32, 8)>>>(qh + 2ull * NE, ql + 2ull * NE, vth, vtl);
    // scores: per batch S[2048,2048] = Q x K^T, scale 1/32
    gemm_bf16x3<1><<<dim3(16, 16, 4), 128, SMEM_BYTES>>>(
        qh, ql, qh + NE, ql + NE,
        1024, 1024, 2048, 1024,
        (size_t)2048 * 1024, (size_t)2048 * 1024, (size_t)2048 * 2048,
        nullptr, 0, 0.03125f, Sb, nullptr, nullptr);
    softmax_split<<<8192, 256>>>(Sb, ph, pl);
    // O = P x V (B operand = V^T rows, K-major over s)
    gemm_bf16x3<1><<<dim3(8, 16, 4), 128, SMEM_BYTES>>>(
        ph, pl, vth, vtl,
        2048, 2048, 1024, 2048,
        (size_t)2048 * 2048, (size_t)1024 * 2048, (size_t)2048 * 1024,
        nullptr, 0, 1.0f, out, nullptr, nullptr);
}

// round 7
// speedup vs baseline: 1.5328x; 1.3497x over previous
#include <cuda_runtime.h>
#include <cuda_fp16.h>
#include <cstdint>
#include <cstddef>

// ---------------- helpers ----------------
__device__ __forceinline__ uint32_t smem_u32(const void* p) {
    uint32_t a;
    asm("{ .reg .u64 t; cvta.to.shared.u64 t, %1; cvt.u32.u64 %0, t; }" : "=r"(a) : "l"(p));
    return a;
}
__device__ __forceinline__ void ldm_x4(uint32_t* r, uint32_t addr) {
    asm volatile("ldmatrix.sync.aligned.m8n8.x4.shared.b16 {%0,%1,%2,%3}, [%4];"
                 : "=r"(r[0]), "=r"(r[1]), "=r"(r[2]), "=r"(r[3]) : "r"(addr));
}
__device__ __forceinline__ void mma_f16(float* c, const uint32_t* a, const uint32_t* b) {
    asm volatile("mma.sync.aligned.m16n8k16.row.col.f32.f16.f16.f32 "
                 "{%0,%1,%2,%3}, {%4,%5,%6,%7}, {%8,%9}, {%0,%1,%2,%3};"
                 : "+f"(c[0]), "+f"(c[1]), "+f"(c[2]), "+f"(c[3])
                 : "r"(a[0]), "r"(a[1]), "r"(a[2]), "r"(a[3]), "r"(b[0]), "r"(b[1]));
}
#define CP_ASYNC16(dst, src) \
    asm volatile("cp.async.cg.shared.global [%0], [%1], 16;" :: "r"(dst), "l"(src))
#define CP_COMMIT() asm volatile("cp.async.commit_group;" ::: "memory")

// ---------------- problem constants ----------------
#define NE 8388608            // 4*2048*1024
#define NS 16777216           // 4*2048*2048
#define WN 1048576            // 1024*1024

static constexpr int BK = 32;
static constexpr int SST = 40;                      // smem row stride (half): 80B
static constexpr uint32_t MATB = 128 * SST * 2;     // 10240 per 128x32 tile
static constexpr uint32_t OFF_AH = 0;
static constexpr uint32_t OFF_AL = MATB;
static constexpr uint32_t OFF_B  = 2 * MATB;
static constexpr uint32_t STAGEB = 3 * MATB;        // 30720
static constexpr unsigned SMEM_BYTES = 2 * STAGEB;  // 61440

// ---------------- scratch (device globals) ----------------
__device__ __align__(256) __half g_xh[3ull * NE];
__device__ __align__(256) __half g_xl[3ull * NE];
__device__ __align__(256) __half g_wt[3ull * WN];    // W^T single fp16
__device__ __align__(256) __half g_qh[3ull * NE];    // Q/K/V hi
__device__ __align__(256) __half g_ql[3ull * NE];    // Q/K/V lo (used for Q and P paths)
__device__ __align__(256) __half g_vt[NE];           // V^T single fp16
__device__ __align__(256) float  g_S[NS];
__device__ __align__(256) __half g_ph[NS];
__device__ __align__(256) __half g_pl[NS];
__device__ __align__(256) float  g_bias[3072];

// ---------------- small kernels ----------------
__global__ void pack_bias(const float* __restrict__ bq, const float* __restrict__ bk,
                          const float* __restrict__ bv, float* __restrict__ dst) {
    int i = blockIdx.x * blockDim.x + threadIdx.x;  // 0..3071
    const float* s = (i < 1024) ? bq : (i < 2048) ? bk : bv;
    dst[i] = s[i & 1023];
}

// split three fp32 inputs into fp16 hi/lo
__global__ void split_all(const float* __restrict__ q, const float* __restrict__ k,
                          const float* __restrict__ v, __half* __restrict__ hi,
                          __half* __restrict__ lo) {
    const int z = blockIdx.z;
    const float* in = (z == 0) ? q : (z == 1) ? k : v;
    size_t base = (size_t)z * NE;
    size_t li = ((size_t)blockIdx.x * blockDim.x + threadIdx.x) * 4;
    size_t i = base + li;
    float4 vv = *reinterpret_cast<const float4*>(in + li);
    float f[4] = {vv.x, vv.y, vv.z, vv.w};
    __half h[4], l[4];
#pragma unroll
    for (int j = 0; j < 4; j++) {
        h[j] = __float2half(f[j]);
        l[j] = __float2half(f[j] - __half2float(h[j]));
    }
    reinterpret_cast<__half2*>(hi + i)[0] = __halves2half2(h[0], h[1]);
    reinterpret_cast<__half2*>(hi + i)[1] = __halves2half2(h[2], h[3]);
    reinterpret_cast<__half2*>(lo + i)[0] = __halves2half2(l[0], l[1]);
    reinterpret_cast<__half2*>(lo + i)[1] = __halves2half2(l[2], l[3]);
}

// W[d][n] f32 -> Wt [n][d] fp16 (single rounding), z selects weight
__global__ void wtrans_all(const float* __restrict__ Wq, const float* __restrict__ Wk,
                           const float* __restrict__ Wv, __half* __restrict__ o) {
    __shared__ float t[32][33];
    const int z = blockIdx.z;
    const float* W = (z == 0) ? Wq : (z == 1) ? Wk : Wv;
    size_t base = (size_t)z * WN;
    int n0 = blockIdx.x * 32, k0 = blockIdx.y * 32;
    int tx = threadIdx.x, ty = threadIdx.y;
#pragma unroll
    for (int i = 0; i < 4; i++)
        t[ty + i * 8][tx] = W[(size_t)(k0 + ty + i * 8) * 1024 + n0 + tx];
    __syncthreads();
#pragma unroll
    for (int i = 0; i < 4; i++) {
        size_t oo = base + (size_t)(n0 + ty + i * 8) * 1024 + k0 + tx;
        o[oo] = __float2half(t[tx][ty + i * 8]);
    }
}

// V hi [b][s][v] -> Vt [b][v][s] (single fp16)
__global__ void vtrans(const __half* __restrict__ vh, __half* __restrict__ o) {
    __shared__ __half th[32][33];
    int b = blockIdx.z;
    size_t inOff = (size_t)b * 2048 * 1024, outOff = (size_t)b * 1024 * 2048;
    int v0 = blockIdx.x * 32, s0 = blockIdx.y * 32;
    int tx = threadIdx.x, ty = threadIdx.y;
#pragma unroll
    for (int i = 0; i < 4; i++)
        th[ty + i * 8][tx] = vh[inOff + (size_t)(s0 + ty + i * 8) * 1024 + v0 + tx];
    __syncthreads();
#pragma unroll
    for (int i = 0; i < 4; i++)
        o[outOff + (size_t)(v0 + ty + i * 8) * 2048 + s0 + tx] = th[tx][ty + i * 8];
}

// row softmax over 2048 -> split fp16 probs
__global__ void softmax_split(const float* __restrict__ S, __half* __restrict__ ph,
                              __half* __restrict__ pl) {
    const int row = blockIdx.x;
    const float* x = S + (size_t)row * 2048;
    const int tid = threadIdx.x;  // 256
    float v[8];
    float mx = -1e30f;
#pragma unroll
    for (int i = 0; i < 8; i++) { v[i] = x[tid + i * 256]; mx = fmaxf(mx, v[i]); }
#pragma unroll
    for (int o = 16; o; o >>= 1) mx = fmaxf(mx, __shfl_xor_sync(0xFFFFFFFFu, mx, o));
    __shared__ float redm[8], reds[8];
    if ((tid & 31) == 0) redm[tid >> 5] = mx;
    __syncthreads();
    float m2 = redm[0];
#pragma unroll
    for (int w = 1; w < 8; w++) m2 = fmaxf(m2, redm[w]);
    float s = 0.f;
#pragma unroll
    for (int i = 0; i < 8; i++) { v[i] = __expf(v[i] - m2); s += v[i]; }
#pragma unroll
    for (int o = 16; o; o >>= 1) s += __shfl_xor_sync(0xFFFFFFFFu, s, o);
    if ((tid & 31) == 0) reds[tid >> 5] = s;
    __syncthreads();
    float st = 0.f;
#pragma unroll
    for (int w = 0; w < 8; w++) st += reds[w];
    float inv = 1.f / st;
#pragma unroll
    for (int i = 0; i < 8; i++) {
        float p = v[i] * inv;
        __half h = __float2half(p);
        __half l = __float2half(p - __half2float(h));
        size_t o = (size_t)row * 2048 + tid + i * 256;
        ph[o] = h; pl[o] = l;
    }
}

// ---------------- HMMA fp16 asymmetric-split GEMM: C[128x128]/CTA, 4 warps ----------------
// C = (Ah + Al) x B, both fp16; exact up to B's fp16 rounding. 2 MMAs per tile-pair.
// A row-major [M][K], B K-major [N][K].
// MODE 0: split(val + bias[z*biasStride+col]) -> outH/outL fp16 ; MODE 1: outF = val*scale.
template <int MODE>
__global__ void __launch_bounds__(128, 2)
gemm_f16x2(const __half* __restrict__ Ah, const __half* __restrict__ Al,
           const __half* __restrict__ B,
           int lda, int ldb, int ldc, int K,
           size_t aBatch, size_t bBatch, size_t cBatch,
           const float* __restrict__ bias, int biasStride, float scale,
           float* __restrict__ outF, __half* __restrict__ outH, __half* __restrict__ outL) {
    extern __shared__ char sm[];
    const uint32_t sbase = smem_u32(sm);
    const int tid = threadIdx.x;
    const int lane = tid & 31, wid = tid >> 5;
    const int wm = wid >> 1, wn = wid & 1;  // 2x2 warp grid, 64x64 tiles
    const int z = blockIdx.z;
    Ah += (size_t)z * aBatch; Al += (size_t)z * aBatch;
    B  += (size_t)z * bBatch;
    if (MODE == 0) { outH += (size_t)z * cBatch; outL += (size_t)z * cBatch; bias += (size_t)z * biasStride; }
    else           { outF += (size_t)z * cBatch; }

    const int mBase = blockIdx.y * 128;
    const int nBase = blockIdx.x * 128;
    const int KT = K / BK;

    auto load_mat = [&](const __half* g, int ld, int rb, uint32_t dstOff) {
#pragma unroll
        for (int i = 0; i < 4; i++) {
            int idx = tid + i * 128;
            int r = idx >> 2, c = idx & 3;
            uint32_t daddr = dstOff + (uint32_t)(r * SST + c * 8) * 2;
            const void* gp = g + (size_t)(rb + r) * ld + c * 8;
            CP_ASYNC16(daddr, gp);
        }
    };
    auto issue_load = [&](int kb, int stage) {
        const int kOff = kb * BK;
        const uint32_t sb = sbase + stage * STAGEB;
        load_mat(Ah + kOff, lda, mBase, sb + OFF_AH);
        load_mat(Al + kOff, lda, mBase, sb + OFF_AL);
        load_mat(B + kOff, ldb, nBase, sb + OFF_B);
        CP_COMMIT();
    };

    float acc[4][8][4];
#pragma unroll
    for (int i = 0; i < 4; i++)
#pragma unroll
        for (int j = 0; j < 8; j++)
#pragma unroll
            for (int e = 0; e < 4; e++) acc[i][j][e] = 0.f;

    issue_load(0, 0);

    for (int kb = 0; kb < KT; kb++) {
        if (kb + 1 < KT) {
            issue_load(kb + 1, (kb + 1) & 1);
            asm volatile("cp.async.wait_group 1;" ::: "memory");
        } else {
            asm volatile("cp.async.wait_group 0;" ::: "memory");
        }
        __syncthreads();

        const uint32_t sb = sbase + (kb & 1) * STAGEB;
#pragma unroll
        for (int ks = 0; ks < 2; ks++) {
            // A fragments hi & lo, 4 m-tiles (64 rows)
            uint32_t ah[4][4], al[4][4];
            const int rowA = wm * 64 + (lane & 15);
            const int colA = ks * 16 + (lane >> 4) * 8;
#pragma unroll
            for (int mt = 0; mt < 4; mt++) {
                uint32_t off = (uint32_t)((rowA + mt * 16) * SST + colA) * 2;
                ldm_x4(ah[mt], sb + OFF_AH + off);
                ldm_x4(al[mt], sb + OFF_AL + off);
            }
            // B: 8 n-tiles in 4 pairs; per pair one ldmatrix, 2 products
            const int rB = wn * 64 + ((lane >> 4) << 3) + (lane & 7);
            const int cB = ks * 16 + (((lane >> 3) & 1) << 3);
#pragma unroll
            for (int bp = 0; bp < 4; bp++) {
                uint32_t off = (uint32_t)((rB + bp * 16) * SST + cB) * 2;
                uint32_t th[4];
                ldm_x4(th, sb + OFF_B + off);
#pragma unroll
                for (int mt = 0; mt < 4; mt++) {
                    mma_f16(acc[mt][bp * 2 + 0], ah[mt], th + 0);
                    mma_f16(acc[mt][bp * 2 + 1], ah[mt], th + 2);
                }
#pragma unroll
                for (int mt = 0; mt < 4; mt++) {
                    mma_f16(acc[mt][bp * 2 + 0], al[mt], th + 0);
                    mma_f16(acc[mt][bp * 2 + 1], al[mt], th + 2);
                }
            }
        }
        __syncthreads();
    }

    // epilogue
    const int g = lane >> 2, tq = lane & 3;
#pragma unroll
    for (int mt = 0; mt < 4; mt++) {
        const int row = mBase + wm * 64 + mt * 16 + g;
#pragma unroll
        for (int nt = 0; nt < 8; nt++) {
            const int col = nBase + wn * 64 + nt * 8 + tq * 2;
            const float* c = acc[mt][nt];
            if (MODE == 0) {
                float b0 = bias[col], b1 = bias[col + 1];
#pragma unroll
                for (int half_ = 0; half_ < 2; half_++) {
                    int rr = row + half_ * 8;
                    float v0 = c[half_ * 2 + 0] + b0;
                    float v1 = c[half_ * 2 + 1] + b1;
                    __half h0 = __float2half(v0);
                    __half h1 = __float2half(v1);
                    __half l0 = __float2half(v0 - __half2float(h0));
                    __half l1 = __float2half(v1 - __half2float(h1));
                    size_t o = (size_t)rr * ldc + col;
                    *reinterpret_cast<__half2*>(outH + o) = __halves2half2(h0, h1);
                    *reinterpret_cast<__half2*>(outL + o) = __halves2half2(l0, l1);
                }
            } else {
                float2 v0 = {c[0] * scale, c[1] * scale};
                float2 v1 = {c[2] * scale, c[3] * scale};
                *reinterpret_cast<float2*>(outF + (size_t)row * ldc + col) = v0;
                *reinterpret_cast<float2*>(outF + (size_t)(row + 8) * ldc + col) = v1;
            }
        }
    }
}

// ---------------- launch ----------------
extern "C" void kernel_launch(void* const* d_in, const int* in_sizes, int n_in,
                              void* d_out, int out_size) {
    const float* q_in = (const float*)d_in[0];
    const float* k_in = (const float*)d_in[1];
    const float* v_in = (const float*)d_in[2];
    const float* Wq   = (const float*)d_in[3];
    const float* bq   = (const float*)d_in[4];
    const float* Wk   = (const float*)d_in[5];
    const float* bk   = (const float*)d_in[6];
    const float* Wv   = (const float*)d_in[7];
    const float* bv   = (const float*)d_in[8];
    float* out = (float*)d_out;

    cudaFuncSetAttribute(gemm_f16x2<0>, cudaFuncAttributeMaxDynamicSharedMemorySize, SMEM_BYTES);
    cudaFuncSetAttribute(gemm_f16x2<1>, cudaFuncAttributeMaxDynamicSharedMemorySize, SMEM_BYTES);

    void* p;
    cudaGetSymbolAddress(&p, g_xh);  __half* xh = (__half*)p;
    cudaGetSymbolAddress(&p, g_xl);  __half* xl = (__half*)p;
    cudaGetSymbolAddress(&p, g_wt);  __half* wt = (__half*)p;
    cudaGetSymbolAddress(&p, g_qh);  __half* qh = (__half*)p;
    cudaGetSymbolAddress(&p, g_ql);  __half* ql = (__half*)p;
    cudaGetSymbolAddress(&p, g_vt);  __half* vt = (__half*)p;
    cudaGetSymbolAddress(&p, g_S);   float* Sb = (float*)p;
    cudaGetSymbolAddress(&p, g_ph);  __half* ph = (__half*)p;
    cudaGetSymbolAddress(&p, g_pl);  __half* pl = (__half*)p;
    cudaGetSymbolAddress(&p, g_bias); float* bias = (float*)p;

    // launch 0: pack biases
    pack_bias<<<12, 256>>>(bq, bk, bv, bias);
    // launch 1,2: prep
    split_all<<<dim3(8192, 1, 3), 256>>>(q_in, k_in, v_in, xh, xl);
    wtrans_all<<<dim3(32, 32, 3), dim3(32, 8)>>>(Wq, Wk, Wv, wt);
    // launch 3: all 3 projections, z = q/k/v: [8192,1024] = X x W + b -> split fp16
    gemm_f16x2<0><<<dim3(8, 64, 3), 128, SMEM_BYTES>>>(
        xh, xl, wt,
        1024, 1024, 1024, 1024,
        (size_t)NE, (size_t)WN, (size_t)NE,
        bias, 1024, 0.f, nullptr, qh, ql);
    // launch 4: transpose V (single fp16)
    vtrans<<<dim3(32, 64, 4), dim3(32, 8)>>>(qh + 2ull * NE, vt);
    // launch 5 (ncu target): scores S[2048,2048] = Q x K^T, scale 1/32
    gemm_f16x2<1><<<dim3(16, 16, 4), 128, SMEM_BYTES>>>(
        qh, ql, qh + NE,
        1024, 1024, 2048, 1024,
        (size_t)2048 * 1024, (size_t)2048 * 1024, (size_t)2048 * 2048,
        nullptr, 0, 0.03125f, Sb, nullptr, nullptr);
    // launch 6: softmax -> split fp16 probs
    softmax_split<<<8192, 256>>>(Sb, ph, pl);
    // launch 7: O = P x V (B operand = V^T rows, K-major over s)
    gemm_f16x2<1><<<dim3(8, 16, 4), 128, SMEM_BYTES>>>(
        ph, pl, vt,
        2048, 2048, 1024, 2048,
        (size_t)2048 * 2048, (size_t)1024 * 2048, (size_t)2048 * 1024,
        nullptr, 0, 1.0f, out, nullptr, nullptr);
}

// round 8
// speedup vs baseline: 1.8401x; 1.2004x over previous
#include <cuda_runtime.h>
#include <cuda_fp16.h>
#include <cstdint>
#include <cstddef>

// ---------------- helpers ----------------
__device__ __forceinline__ uint32_t smem_u32(const void* p) {
    uint32_t a;
    asm("{ .reg .u64 t; cvta.to.shared.u64 t, %1; cvt.u32.u64 %0, t; }" : "=r"(a) : "l"(p));
    return a;
}
__device__ __forceinline__ void ldm_x4(uint32_t* r, uint32_t addr) {
    asm volatile("ldmatrix.sync.aligned.m8n8.x4.shared.b16 {%0,%1,%2,%3}, [%4];"
                 : "=r"(r[0]), "=r"(r[1]), "=r"(r[2]), "=r"(r[3]) : "r"(addr));
}
__device__ __forceinline__ void mma_f16(float* c, const uint32_t* a, const uint32_t* b) {
    asm volatile("mma.sync.aligned.m16n8k16.row.col.f32.f16.f16.f32 "
                 "{%0,%1,%2,%3}, {%4,%5,%6,%7}, {%8,%9}, {%0,%1,%2,%3};"
                 : "+f"(c[0]), "+f"(c[1]), "+f"(c[2]), "+f"(c[3])
                 : "r"(a[0]), "r"(a[1]), "r"(a[2]), "r"(a[3]), "r"(b[0]), "r"(b[1]));
}
#define CP_ASYNC16(dst, src) \
    asm volatile("cp.async.cg.shared.global [%0], [%1], 16;" :: "r"(dst), "l"(src))
#define CP_COMMIT() asm volatile("cp.async.commit_group;" ::: "memory")
#define CP_WAIT1() asm volatile("cp.async.wait_group 1;" ::: "memory")
#define CP_WAIT0() asm volatile("cp.async.wait_group 0;" ::: "memory")

// ---------------- problem constants ----------------
#define NE 8388608            // 4*2048*1024
#define NS 16777216           // 4*2048*2048
#define WN 1048576            // 1024*1024

static constexpr int BK = 32;
static constexpr int SST = 40;                      // smem row stride (half): 80B
static constexpr uint32_t MATB = 128 * SST * 2;     // 10240 per 128x32 tile

// ---------------- scratch (device globals) ----------------
__device__ __align__(256) __half g_xh[3ull * NE];
__device__ __align__(256) __half g_xl[3ull * NE];
__device__ __align__(256) __half g_wt[3ull * WN];    // W^T single fp16
__device__ __align__(256) __half g_qh[3ull * NE];    // Q/K/V hi
__device__ __align__(256) __half g_ql[3ull * NE];    // Q/K/V lo
__device__ __align__(256) __half g_vt[NE];           // V^T single fp16
__device__ __align__(256) float  g_S[NS];
__device__ __align__(256) __half g_ph[NS];           // softmax probs (single fp16)
__device__ __align__(256) float  g_bias[3072];

// ---------------- small kernels ----------------
__global__ void pack_bias(const float* __restrict__ bq, const float* __restrict__ bk,
                          const float* __restrict__ bv, float* __restrict__ dst) {
    int i = blockIdx.x * blockDim.x + threadIdx.x;  // 0..3071
    const float* s = (i < 1024) ? bq : (i < 2048) ? bk : bv;
    dst[i] = s[i & 1023];
}

__global__ void split_all(const float* __restrict__ q, const float* __restrict__ k,
                          const float* __restrict__ v, __half* __restrict__ hi,
                          __half* __restrict__ lo) {
    const int z = blockIdx.z;
    const float* in = (z == 0) ? q : (z == 1) ? k : v;
    size_t base = (size_t)z * NE;
    size_t li = ((size_t)blockIdx.x * blockDim.x + threadIdx.x) * 4;
    size_t i = base + li;
    float4 vv = *reinterpret_cast<const float4*>(in + li);
    float f[4] = {vv.x, vv.y, vv.z, vv.w};
    __half h[4], l[4];
#pragma unroll
    for (int j = 0; j < 4; j++) {
        h[j] = __float2half(f[j]);
        l[j] = __float2half(f[j] - __half2float(h[j]));
    }
    reinterpret_cast<__half2*>(hi + i)[0] = __halves2half2(h[0], h[1]);
    reinterpret_cast<__half2*>(hi + i)[1] = __halves2half2(h[2], h[3]);
    reinterpret_cast<__half2*>(lo + i)[0] = __halves2half2(l[0], l[1]);
    reinterpret_cast<__half2*>(lo + i)[1] = __halves2half2(l[2], l[3]);
}

__global__ void wtrans_all(const float* __restrict__ Wq, const float* __restrict__ Wk,
                           const float* __restrict__ Wv, __half* __restrict__ o) {
    __shared__ float t[32][33];
    const int z = blockIdx.z;
    const float* W = (z == 0) ? Wq : (z == 1) ? Wk : Wv;
    size_t base = (size_t)z * WN;
    int n0 = blockIdx.x * 32, k0 = blockIdx.y * 32;
    int tx = threadIdx.x, ty = threadIdx.y;
#pragma unroll
    for (int i = 0; i < 4; i++)
        t[ty + i * 8][tx] = W[(size_t)(k0 + ty + i * 8) * 1024 + n0 + tx];
    __syncthreads();
#pragma unroll
    for (int i = 0; i < 4; i++) {
        size_t oo = base + (size_t)(n0 + ty + i * 8) * 1024 + k0 + tx;
        o[oo] = __float2half(t[tx][ty + i * 8]);
    }
}

__global__ void vtrans(const __half* __restrict__ vh, __half* __restrict__ o) {
    __shared__ __half th[32][33];
    int b = blockIdx.z;
    size_t inOff = (size_t)b * 2048 * 1024, outOff = (size_t)b * 1024 * 2048;
    int v0 = blockIdx.x * 32, s0 = blockIdx.y * 32;
    int tx = threadIdx.x, ty = threadIdx.y;
#pragma unroll
    for (int i = 0; i < 4; i++)
        th[ty + i * 8][tx] = vh[inOff + (size_t)(s0 + ty + i * 8) * 1024 + v0 + tx];
    __syncthreads();
#pragma unroll
    for (int i = 0; i < 4; i++)
        o[outOff + (size_t)(v0 + ty + i * 8) * 2048 + s0 + tx] = th[tx][ty + i * 8];
}

// row softmax over 2048 -> single fp16 probs
__global__ void softmax_h(const float* __restrict__ S, __half* __restrict__ ph) {
    const int row = blockIdx.x;
    const float* x = S + (size_t)row * 2048;
    const int tid = threadIdx.x;  // 256
    float v[8];
    float mx = -1e30f;
#pragma unroll
    for (int i = 0; i < 8; i++) { v[i] = x[tid + i * 256]; mx = fmaxf(mx, v[i]); }
#pragma unroll
    for (int o = 16; o; o >>= 1) mx = fmaxf(mx, __shfl_xor_sync(0xFFFFFFFFu, mx, o));
    __shared__ float redm[8], reds[8];
    if ((tid & 31) == 0) redm[tid >> 5] = mx;
    __syncthreads();
    float m2 = redm[0];
#pragma unroll
    for (int w = 1; w < 8; w++) m2 = fmaxf(m2, redm[w]);
    float s = 0.f;
#pragma unroll
    for (int i = 0; i < 8; i++) { v[i] = __expf(v[i] - m2); s += v[i]; }
#pragma unroll
    for (int o = 16; o; o >>= 1) s += __shfl_xor_sync(0xFFFFFFFFu, s, o);
    if ((tid & 31) == 0) reds[tid >> 5] = s;
    __syncthreads();
    float st = 0.f;
#pragma unroll
    for (int w = 0; w < 8; w++) st += reds[w];
    float inv = 1.f / st;
#pragma unroll
    for (int i = 0; i < 8; i++)
        ph[(size_t)row * 2048 + tid + i * 256] = __float2half(v[i] * inv);
}

// ---------------- HMMA GEMM: C[128x128]/CTA, 4 warps, 3-stage pipeline ----------------
// NPROD=2: C = (Ah+Al) x B (A split).  NPROD=1: C = Ah x B.
// A row-major [M][K], B K-major [N][K].
// MODE 0: split(val + bias[z*biasStride+col]) -> outH/outL ; MODE 1: outF = val*scale.
template <int MODE, int NPROD>
__global__ void __launch_bounds__(128, 2)
gemm_f16(const __half* __restrict__ Ah, const __half* __restrict__ Al,
         const __half* __restrict__ B,
         int lda, int ldb, int ldc, int K,
         size_t aBatch, size_t bBatch, size_t cBatch,
         const float* __restrict__ bias, int biasStride, float scale,
         float* __restrict__ outF, __half* __restrict__ outH, __half* __restrict__ outL) {
    constexpr uint32_t OFF_AH = 0;
    constexpr uint32_t OFF_AL = MATB;                       // only if NPROD==2
    constexpr uint32_t OFF_B  = NPROD * MATB;
    constexpr uint32_t STAGEB = (NPROD + 1) * MATB;

    extern __shared__ char sm[];
    const uint32_t sbase = smem_u32(sm);
    const int tid = threadIdx.x;
    const int lane = tid & 31, wid = tid >> 5;
    const int wm = wid >> 1, wn = wid & 1;  // 2x2 warp grid, 64x64 tiles
    const int z = blockIdx.z;
    Ah += (size_t)z * aBatch;
    if (NPROD == 2) Al += (size_t)z * aBatch;
    B += (size_t)z * bBatch;
    if (MODE == 0) { outH += (size_t)z * cBatch; outL += (size_t)z * cBatch; bias += (size_t)z * biasStride; }
    else           { outF += (size_t)z * cBatch; }

    const int mBase = blockIdx.y * 128;
    const int nBase = blockIdx.x * 128;
    const int KT = K / BK;

    auto load_mat = [&](const __half* g, int ld, int rb, uint32_t dstOff) {
#pragma unroll
        for (int i = 0; i < 4; i++) {
            int idx = tid + i * 128;
            int r = idx >> 2, c = idx & 3;
            uint32_t daddr = dstOff + (uint32_t)(r * SST + c * 8) * 2;
            const void* gp = g + (size_t)(rb + r) * ld + c * 8;
            CP_ASYNC16(daddr, gp);
        }
    };
    auto issue_load = [&](int kb, int stage) {
        const int kOff = kb * BK;
        const uint32_t sb = sbase + stage * STAGEB;
        load_mat(Ah + kOff, lda, mBase, sb + OFF_AH);
        if (NPROD == 2) load_mat(Al + kOff, lda, mBase, sb + OFF_AL);
        load_mat(B + kOff, ldb, nBase, sb + OFF_B);
        CP_COMMIT();
    };

    float acc[4][8][4];
#pragma unroll
    for (int i = 0; i < 4; i++)
#pragma unroll
        for (int j = 0; j < 8; j++)
#pragma unroll
            for (int e = 0; e < 4; e++) acc[i][j][e] = 0.f;

    // prologue: stages 0,1
    issue_load(0, 0);
    if (KT > 1) issue_load(1, 1);

    int stage = 0, nstage = 2;  // nstage = (kb+2) % 3
    for (int kb = 0; kb < KT; kb++) {
        if (kb == KT - 1) { CP_WAIT0(); } else { CP_WAIT1(); }
        __syncthreads();
        if (kb + 2 < KT) issue_load(kb + 2, nstage);

        const uint32_t sb = sbase + (uint32_t)stage * STAGEB;
#pragma unroll
        for (int ks = 0; ks < 2; ks++) {
            uint32_t ah[4][4], al[4][4];
            const int rowA = wm * 64 + (lane & 15);
            const int colA = ks * 16 + (lane >> 4) * 8;
#pragma unroll
            for (int mt = 0; mt < 4; mt++) {
                uint32_t off = (uint32_t)((rowA + mt * 16) * SST + colA) * 2;
                ldm_x4(ah[mt], sb + OFF_AH + off);
                if (NPROD == 2) ldm_x4(al[mt], sb + OFF_AL + off);
            }
            const int rB = wn * 64 + ((lane >> 4) << 3) + (lane & 7);
            const int cB = ks * 16 + (((lane >> 3) & 1) << 3);
#pragma unroll
            for (int bp = 0; bp < 4; bp++) {
                uint32_t off = (uint32_t)((rB + bp * 16) * SST + cB) * 2;
                uint32_t th[4];
                ldm_x4(th, sb + OFF_B + off);
#pragma unroll
                for (int mt = 0; mt < 4; mt++) {
                    mma_f16(acc[mt][bp * 2 + 0], ah[mt], th + 0);
                    mma_f16(acc[mt][bp * 2 + 1], ah[mt], th + 2);
                }
                if (NPROD == 2) {
#pragma unroll
                    for (int mt = 0; mt < 4; mt++) {
                        mma_f16(acc[mt][bp * 2 + 0], al[mt], th + 0);
                        mma_f16(acc[mt][bp * 2 + 1], al[mt], th + 2);
                    }
                }
            }
        }
        stage = (stage == 2) ? 0 : stage + 1;
        nstage = (nstage == 2) ? 0 : nstage + 1;
    }

    // epilogue
    const int g = lane >> 2, tq = lane & 3;
#pragma unroll
    for (int mt = 0; mt < 4; mt++) {
        const int row = mBase + wm * 64 + mt * 16 + g;
#pragma unroll
        for (int nt = 0; nt < 8; nt++) {
            const int col = nBase + wn * 64 + nt * 8 + tq * 2;
            const float* c = acc[mt][nt];
            if (MODE == 0) {
                float b0 = bias[col], b1 = bias[col + 1];
#pragma unroll
                for (int half_ = 0; half_ < 2; half_++) {
                    int rr = row + half_ * 8;
                    float v0 = c[half_ * 2 + 0] + b0;
                    float v1 = c[half_ * 2 + 1] + b1;
                    __half h0 = __float2half(v0);
                    __half h1 = __float2half(v1);
                    __half l0 = __float2half(v0 - __half2float(h0));
                    __half l1 = __float2half(v1 - __half2float(h1));
                    size_t o = (size_t)rr * ldc + col;
                    *reinterpret_cast<__half2*>(outH + o) = __halves2half2(h0, h1);
                    *reinterpret_cast<__half2*>(outL + o) = __halves2half2(l0, l1);
                }
            } else {
                float2 v0 = {c[0] * scale, c[1] * scale};
                float2 v1 = {c[2] * scale, c[3] * scale};
                *reinterpret_cast<float2*>(outF + (size_t)row * ldc + col) = v0;
                *reinterpret_cast<float2*>(outF + (size_t)(row + 8) * ldc + col) = v1;
            }
        }
    }
}

// ---------------- launch ----------------
extern "C" void kernel_launch(void* const* d_in, const int* in_sizes, int n_in,
                              void* d_out, int out_size) {
    const float* q_in = (const float*)d_in[0];
    const float* k_in = (const float*)d_in[1];
    const float* v_in = (const float*)d_in[2];
    const float* Wq   = (const float*)d_in[3];
    const float* bq   = (const float*)d_in[4];
    const float* Wk   = (const float*)d_in[5];
    const float* bk   = (const float*)d_in[6];
    const float* Wv   = (const float*)d_in[7];
    const float* bv   = (const float*)d_in[8];
    float* out = (float*)d_out;

    constexpr unsigned SMEM2 = 3 * 3 * MATB;  // NPROD=2: 92160
    constexpr unsigned SMEM1 = 3 * 2 * MATB;  // NPROD=1: 61440
    cudaFuncSetAttribute((gemm_f16<0, 2>), cudaFuncAttributeMaxDynamicSharedMemorySize, SMEM2);
    cudaFuncSetAttribute((gemm_f16<1, 2>), cudaFuncAttributeMaxDynamicSharedMemorySize, SMEM2);
    cudaFuncSetAttribute((gemm_f16<1, 1>), cudaFuncAttributeMaxDynamicSharedMemorySize, SMEM1);

    void* p;
    cudaGetSymbolAddress(&p, g_xh);  __half* xh = (__half*)p;
    cudaGetSymbolAddress(&p, g_xl);  __half* xl = (__half*)p;
    cudaGetSymbolAddress(&p, g_wt);  __half* wt = (__half*)p;
    cudaGetSymbolAddress(&p, g_qh);  __half* qh = (__half*)p;
    cudaGetSymbolAddress(&p, g_ql);  __half* ql = (__half*)p;
    cudaGetSymbolAddress(&p, g_vt);  __half* vt = (__half*)p;
    cudaGetSymbolAddress(&p, g_S);   float* Sb = (float*)p;
    cudaGetSymbolAddress(&p, g_ph);  __half* ph = (__half*)p;
    cudaGetSymbolAddress(&p, g_bias); float* bias = (float*)p;

    pack_bias<<<12, 256>>>(bq, bk, bv, bias);
    split_all<<<dim3(8192, 1, 3), 256>>>(q_in, k_in, v_in, xh, xl);
    wtrans_all<<<dim3(32, 32, 3), dim3(32, 8)>>>(Wq, Wk, Wv, wt);
    // all 3 projections (z = q/k/v): [8192,1024] = (Xh+Xl) x W^T + b -> split fp16
    gemm_f16<0, 2><<<dim3(8, 64, 3), 128, SMEM2>>>(
        xh, xl, wt,
        1024, 1024, 1024, 1024,
        (size_t)NE, (size_t)WN, (size_t)NE,
        bias, 1024, 0.f, nullptr, qh, ql);
    vtrans<<<dim3(32, 64, 4), dim3(32, 8)>>>(qh + 2ull * NE, vt);
    // scores (ncu target): S[2048,2048] = (Qh+Ql) x K^T, scale 1/32
    gemm_f16<1, 2><<<dim3(16, 16, 4), 128, SMEM2>>>(
        qh, ql, qh + NE,
        1024, 1024, 2048, 1024,
        (size_t)2048 * 1024, (size_t)2048 * 1024, (size_t)2048 * 2048,
        nullptr, 0, 0.03125f, Sb, nullptr, nullptr);
    softmax_h<<<8192, 256>>>(Sb, ph);
    // O = P x V (single-product; B operand = V^T rows, K-major over s)
    gemm_f16<1, 1><<<dim3(8, 16, 4), 128, SMEM1>>>(
        ph, nullptr, vt,
        2048, 2048, 1024, 2048,
        (size_t)2048 * 2048, (size_t)1024 * 2048, (size_t)2048 * 1024,
        nullptr, 0, 1.0f, out, nullptr, nullptr);
}

// round 9
// speedup vs baseline: 2.9196x; 1.5867x over previous
#include <cuda_runtime.h>
#include <cuda_fp16.h>
#include <cstdint>
#include <cstddef>

// ---------------- helpers ----------------
__device__ __forceinline__ uint32_t smem_u32(const void* p) {
    uint32_t a;
    asm("{ .reg .u64 t; cvta.to.shared.u64 t, %1; cvt.u32.u64 %0, t; }" : "=r"(a) : "l"(p));
    return a;
}
__device__ __forceinline__ void ldm_x4(uint32_t* r, uint32_t addr) {
    asm volatile("ldmatrix.sync.aligned.m8n8.x4.shared.b16 {%0,%1,%2,%3}, [%4];"
                 : "=r"(r[0]), "=r"(r[1]), "=r"(r[2]), "=r"(r[3]) : "r"(addr));
}
__device__ __forceinline__ void mma_f16(float* c, const uint32_t* a, const uint32_t* b) {
    asm volatile("mma.sync.aligned.m16n8k16.row.col.f32.f16.f16.f32 "
                 "{%0,%1,%2,%3}, {%4,%5,%6,%7}, {%8,%9}, {%0,%1,%2,%3};"
                 : "+f"(c[0]), "+f"(c[1]), "+f"(c[2]), "+f"(c[3])
                 : "r"(a[0]), "r"(a[1]), "r"(a[2]), "r"(a[3]), "r"(b[0]), "r"(b[1]));
}
#define CP_ASYNC16(dst, src) \
    asm volatile("cp.async.cg.shared.global [%0], [%1], 16;" :: "r"(dst), "l"(src))
#define CP_COMMIT() asm volatile("cp.async.commit_group;" ::: "memory")
#define CP_WAIT2() asm volatile("cp.async.wait_group 2;" ::: "memory")
#define CP_WAIT1() asm volatile("cp.async.wait_group 1;" ::: "memory")
#define CP_WAIT0() asm volatile("cp.async.wait_group 0;" ::: "memory")

// ---------------- problem constants ----------------
#define NE 8388608            // 4*2048*1024
#define NS 16777216           // 4*2048*2048
#define WN 1048576            // 1024*1024

static constexpr int BK = 32;
static constexpr int SST = 40;                      // smem row stride (half): 80B
static constexpr uint32_t MATB = 128 * SST * 2;     // 10240 per 128x32 tile
static constexpr uint32_t STAGEB = 2 * MATB;        // A + B per stage: 20480
static constexpr unsigned SMEM_BYTES = 4 * STAGEB;  // 4 stages: 81920

// ---------------- scratch (device globals) ----------------
__device__ __align__(256) __half g_x[3ull * NE];     // fp16 inputs
__device__ __align__(256) __half g_wt[3ull * WN];    // W^T fp16
__device__ __align__(256) __half g_qkv[3ull * NE];   // Q/K/V fp16
__device__ __align__(256) __half g_vt[NE];           // V^T fp16
__device__ __align__(256) float  g_S[NS];
__device__ __align__(256) __half g_ph[NS];           // softmax probs fp16
__device__ __align__(256) float  g_bias[3072];

// ---------------- small kernels ----------------
__global__ void pack_bias(const float* __restrict__ bq, const float* __restrict__ bk,
                          const float* __restrict__ bv, float* __restrict__ dst) {
    int i = blockIdx.x * blockDim.x + threadIdx.x;  // 0..3071
    const float* s = (i < 1024) ? bq : (i < 2048) ? bk : bv;
    dst[i] = s[i & 1023];
}

// fp32 -> fp16 convert, three tensors (z selects)
__global__ void cvt_all(const float* __restrict__ q, const float* __restrict__ k,
                        const float* __restrict__ v, __half* __restrict__ o) {
    const int z = blockIdx.z;
    const float* in = (z == 0) ? q : (z == 1) ? k : v;
    size_t li = ((size_t)blockIdx.x * blockDim.x + threadIdx.x) * 4;
    size_t i = (size_t)z * NE + li;
    float4 vv = *reinterpret_cast<const float4*>(in + li);
    reinterpret_cast<__half2*>(o + i)[0] = __halves2half2(__float2half(vv.x), __float2half(vv.y));
    reinterpret_cast<__half2*>(o + i)[1] = __halves2half2(__float2half(vv.z), __float2half(vv.w));
}

// W[d][n] f32 -> Wt [n][d] fp16, z selects weight
__global__ void wtrans_all(const float* __restrict__ Wq, const float* __restrict__ Wk,
                           const float* __restrict__ Wv, __half* __restrict__ o) {
    __shared__ float t[32][33];
    const int z = blockIdx.z;
    const float* W = (z == 0) ? Wq : (z == 1) ? Wk : Wv;
    size_t base = (size_t)z * WN;
    int n0 = blockIdx.x * 32, k0 = blockIdx.y * 32;
    int tx = threadIdx.x, ty = threadIdx.y;
#pragma unroll
    for (int i = 0; i < 4; i++)
        t[ty + i * 8][tx] = W[(size_t)(k0 + ty + i * 8) * 1024 + n0 + tx];
    __syncthreads();
#pragma unroll
    for (int i = 0; i < 4; i++) {
        size_t oo = base + (size_t)(n0 + ty + i * 8) * 1024 + k0 + tx;
        o[oo] = __float2half(t[tx][ty + i * 8]);
    }
}

// V [b][s][v] -> Vt [b][v][s] fp16
__global__ void vtrans(const __half* __restrict__ vh, __half* __restrict__ o) {
    __shared__ __half th[32][33];
    int b = blockIdx.z;
    size_t inOff = (size_t)b * 2048 * 1024, outOff = (size_t)b * 1024 * 2048;
    int v0 = blockIdx.x * 32, s0 = blockIdx.y * 32;
    int tx = threadIdx.x, ty = threadIdx.y;
#pragma unroll
    for (int i = 0; i < 4; i++)
        th[ty + i * 8][tx] = vh[inOff + (size_t)(s0 + ty + i * 8) * 1024 + v0 + tx];
    __syncthreads();
#pragma unroll
    for (int i = 0; i < 4; i++)
        o[outOff + (size_t)(v0 + ty + i * 8) * 2048 + s0 + tx] = th[tx][ty + i * 8];
}

// row softmax over 2048 -> fp16 probs
__global__ void softmax_h(const float* __restrict__ S, __half* __restrict__ ph) {
    const int row = blockIdx.x;
    const float* x = S + (size_t)row * 2048;
    const int tid = threadIdx.x;  // 256
    float v[8];
    float mx = -1e30f;
#pragma unroll
    for (int i = 0; i < 8; i++) { v[i] = x[tid + i * 256]; mx = fmaxf(mx, v[i]); }
#pragma unroll
    for (int o = 16; o; o >>= 1) mx = fmaxf(mx, __shfl_xor_sync(0xFFFFFFFFu, mx, o));
    __shared__ float redm[8], reds[8];
    if ((tid & 31) == 0) redm[tid >> 5] = mx;
    __syncthreads();
    float m2 = redm[0];
#pragma unroll
    for (int w = 1; w < 8; w++) m2 = fmaxf(m2, redm[w]);
    float s = 0.f;
#pragma unroll
    for (int i = 0; i < 8; i++) { v[i] = __expf(v[i] - m2); s += v[i]; }
#pragma unroll
    for (int o = 16; o; o >>= 1) s += __shfl_xor_sync(0xFFFFFFFFu, s, o);
    if ((tid & 31) == 0) reds[tid >> 5] = s;
    __syncthreads();
    float st = 0.f;
#pragma unroll
    for (int w = 0; w < 8; w++) st += reds[w];
    float inv = 1.f / st;
#pragma unroll
    for (int i = 0; i < 8; i++)
        ph[(size_t)row * 2048 + tid + i * 256] = __float2half(v[i] * inv);
}

// ---------------- HMMA fp16 GEMM: C[128x128]/CTA, 4 warps, 4-stage pipeline ----------------
// C = A x B^T. A row-major [M][K], B K-major [N][K].
// MODE 0: outH = fp16(val + bias[z*1024+col]) ; MODE 1: outF = val*scale (fp32).
template <int MODE>
__global__ void __launch_bounds__(128, 2)
gemm_f16(const __half* __restrict__ A, const __half* __restrict__ B,
         int lda, int ldb, int ldc, int K,
         size_t aBatch, size_t bBatch, size_t cBatch,
         const float* __restrict__ bias, float scale,
         float* __restrict__ outF, __half* __restrict__ outH) {
    extern __shared__ char sm[];
    const uint32_t sbase = smem_u32(sm);
    const int tid = threadIdx.x;
    const int lane = tid & 31, wid = tid >> 5;
    const int wm = wid >> 1, wn = wid & 1;  // 2x2 warp grid, 64x64 tiles
    const int z = blockIdx.z;
    A += (size_t)z * aBatch;
    B += (size_t)z * bBatch;
    if (MODE == 0) { outH += (size_t)z * cBatch; bias += (size_t)z * 1024; }
    else           { outF += (size_t)z * cBatch; }

    const int mBase = blockIdx.y * 128;
    const int nBase = blockIdx.x * 128;
    const int KT = K / BK;

    auto load_mat = [&](const __half* g, int ld, int rb, uint32_t dstOff) {
#pragma unroll
        for (int i = 0; i < 4; i++) {
            int idx = tid + i * 128;
            int r = idx >> 2, c = idx & 3;
            uint32_t daddr = dstOff + (uint32_t)(r * SST + c * 8) * 2;
            const void* gp = g + (size_t)(rb + r) * ld + c * 8;
            CP_ASYNC16(daddr, gp);
        }
    };
    auto issue_load = [&](int kb, int stage) {
        const int kOff = kb * BK;
        const uint32_t sb = sbase + (uint32_t)stage * STAGEB;
        load_mat(A + kOff, lda, mBase, sb);
        load_mat(B + kOff, ldb, nBase, sb + MATB);
        CP_COMMIT();
    };

    float acc[4][8][4];
#pragma unroll
    for (int i = 0; i < 4; i++)
#pragma unroll
        for (int j = 0; j < 8; j++)
#pragma unroll
            for (int e = 0; e < 4; e++) acc[i][j][e] = 0.f;

    // prologue: stages 0..2
    issue_load(0, 0);
    issue_load(1, 1);
    issue_load(2, 2);

    for (int kb = 0; kb < KT; kb++) {
        if (kb + 2 < KT)      { CP_WAIT2(); }
        else if (kb + 1 < KT) { CP_WAIT1(); }
        else                  { CP_WAIT0(); }
        __syncthreads();
        if (kb + 3 < KT) issue_load(kb + 3, (kb + 3) & 3);

        const uint32_t sb = sbase + (uint32_t)(kb & 3) * STAGEB;
#pragma unroll
        for (int ks = 0; ks < 2; ks++) {
            uint32_t ah[4][4];
            const int rowA = wm * 64 + (lane & 15);
            const int colA = ks * 16 + (lane >> 4) * 8;
#pragma unroll
            for (int mt = 0; mt < 4; mt++) {
                uint32_t off = (uint32_t)((rowA + mt * 16) * SST + colA) * 2;
                ldm_x4(ah[mt], sb + off);
            }
            const int rB = wn * 64 + ((lane >> 4) << 3) + (lane & 7);
            const int cB = ks * 16 + (((lane >> 3) & 1) << 3);
#pragma unroll
            for (int bp = 0; bp < 4; bp++) {
                uint32_t off = (uint32_t)((rB + bp * 16) * SST + cB) * 2;
                uint32_t th[4];
                ldm_x4(th, sb + MATB + off);
#pragma unroll
                for (int mt = 0; mt < 4; mt++) {
                    mma_f16(acc[mt][bp * 2 + 0], ah[mt], th + 0);
                    mma_f16(acc[mt][bp * 2 + 1], ah[mt], th + 2);
                }
            }
        }
        __syncthreads();
    }

    // epilogue
    const int g = lane >> 2, tq = lane & 3;
#pragma unroll
    for (int mt = 0; mt < 4; mt++) {
        const int row = mBase + wm * 64 + mt * 16 + g;
#pragma unroll
        for (int nt = 0; nt < 8; nt++) {
            const int col = nBase + wn * 64 + nt * 8 + tq * 2;
            const float* c = acc[mt][nt];
            if (MODE == 0) {
                float b0 = bias[col], b1 = bias[col + 1];
#pragma unroll
                for (int h = 0; h < 2; h++) {
                    size_t o = (size_t)(row + h * 8) * ldc + col;
                    *reinterpret_cast<__half2*>(outH + o) =
                        __halves2half2(__float2half(c[h * 2 + 0] + b0),
                                       __float2half(c[h * 2 + 1] + b1));
                }
            } else {
                float2 v0 = {c[0] * scale, c[1] * scale};
                float2 v1 = {c[2] * scale, c[3] * scale};
                *reinterpret_cast<float2*>(outF + (size_t)row * ldc + col) = v0;
                *reinterpret_cast<float2*>(outF + (size_t)(row + 8) * ldc + col) = v1;
            }
        }
    }
}

// ---------------- launch ----------------
extern "C" void kernel_launch(void* const* d_in, const int* in_sizes, int n_in,
                              void* d_out, int out_size) {
    const float* q_in = (const float*)d_in[0];
    const float* k_in = (const float*)d_in[1];
    const float* v_in = (const float*)d_in[2];
    const float* Wq   = (const float*)d_in[3];
    const float* bq   = (const float*)d_in[4];
    const float* Wk   = (const float*)d_in[5];
    const float* bk   = (const float*)d_in[6];
    const float* Wv   = (const float*)d_in[7];
    const float* bv   = (const float*)d_in[8];
    float* out = (float*)d_out;

    cudaFuncSetAttribute((gemm_f16<0>), cudaFuncAttributeMaxDynamicSharedMemorySize, SMEM_BYTES);
    cudaFuncSetAttribute((gemm_f16<1>), cudaFuncAttributeMaxDynamicSharedMemorySize, SMEM_BYTES);

    void* p;
    cudaGetSymbolAddress(&p, g_x);    __half* x  = (__half*)p;
    cudaGetSymbolAddress(&p, g_wt);   __half* wt = (__half*)p;
    cudaGetSymbolAddress(&p, g_qkv);  __half* qkv = (__half*)p;
    cudaGetSymbolAddress(&p, g_vt);   __half* vt = (__half*)p;
    cudaGetSymbolAddress(&p, g_S);    float* Sb = (float*)p;
    cudaGetSymbolAddress(&p, g_ph);   __half* ph = (__half*)p;
    cudaGetSymbolAddress(&p, g_bias); float* bias = (float*)p;

    pack_bias<<<12, 256>>>(bq, bk, bv, bias);
    cvt_all<<<dim3(8192, 1, 3), 256>>>(q_in, k_in, v_in, x);
    wtrans_all<<<dim3(32, 32, 3), dim3(32, 8)>>>(Wq, Wk, Wv, wt);
    // all 3 projections (z = q/k/v): [8192,1024] = X x W^T + b -> fp16
    gemm_f16<0><<<dim3(8, 64, 3), 128, SMEM_BYTES>>>(
        x, wt,
        1024, 1024, 1024, 1024,
        (size_t)NE, (size_t)WN, (size_t)NE,
        bias, 0.f, nullptr, qkv);
    vtrans<<<dim3(32, 64, 4), dim3(32, 8)>>>(qkv + 2ull * NE, vt);
    // scores (ncu target): S[2048,2048] = Q x K^T, scale 1/32
    gemm_f16<1><<<dim3(16, 16, 4), 128, SMEM_BYTES>>>(
        qkv, qkv + NE,
        1024, 1024, 2048, 1024,
        (size_t)2048 * 1024, (size_t)2048 * 1024, (size_t)2048 * 2048,
        nullptr, 0.03125f, Sb, nullptr);
    softmax_h<<<8192, 256>>>(Sb, ph);
    // O = P x V (B operand = V^T rows, K-major over s)
    gemm_f16<1><<<dim3(8, 16, 4), 128, SMEM_BYTES>>>(
        ph, vt,
        2048, 2048, 1024, 2048,
        (size_t)2048 * 2048, (size_t)1024 * 2048, (size_t)2048 * 1024,
        nullptr, 1.0f, out, nullptr);
}

// round 10
// speedup vs baseline: 3.0920x; 1.0590x over previous
#include <cuda_runtime.h>
#include <cuda_fp16.h>
#include <cstdint>
#include <cstddef>

// ---------------- helpers ----------------
__device__ __forceinline__ uint32_t smem_u32(const void* p) {
    uint32_t a;
    asm("{ .reg .u64 t; cvta.to.shared.u64 t, %1; cvt.u32.u64 %0, t; }" : "=r"(a) : "l"(p));
    return a;
}
__device__ __forceinline__ void ldm_x4(uint32_t* r, uint32_t addr) {
    asm volatile("ldmatrix.sync.aligned.m8n8.x4.shared.b16 {%0,%1,%2,%3}, [%4];"
                 : "=r"(r[0]), "=r"(r[1]), "=r"(r[2]), "=r"(r[3]) : "r"(addr));
}
__device__ __forceinline__ void ldm_x4_t(uint32_t* r, uint32_t addr) {
    asm volatile("ldmatrix.sync.aligned.m8n8.x4.trans.shared.b16 {%0,%1,%2,%3}, [%4];"
                 : "=r"(r[0]), "=r"(r[1]), "=r"(r[2]), "=r"(r[3]) : "r"(addr));
}
__device__ __forceinline__ void mma_f16(float* c, const uint32_t* a, const uint32_t* b) {
    asm volatile("mma.sync.aligned.m16n8k16.row.col.f32.f16.f16.f32 "
                 "{%0,%1,%2,%3}, {%4,%5,%6,%7}, {%8,%9}, {%0,%1,%2,%3};"
                 : "+f"(c[0]), "+f"(c[1]), "+f"(c[2]), "+f"(c[3])
                 : "r"(a[0]), "r"(a[1]), "r"(a[2]), "r"(a[3]), "r"(b[0]), "r"(b[1]));
}
#define CP_ASYNC16(dst, src) \
    asm volatile("cp.async.cg.shared.global [%0], [%1], 16;" :: "r"(dst), "l"(src))
#define CP_COMMIT() asm volatile("cp.async.commit_group;" ::: "memory")
#define CP_WAIT3() asm volatile("cp.async.wait_group 3;" ::: "memory")
#define CP_WAIT2() asm volatile("cp.async.wait_group 2;" ::: "memory")
#define CP_WAIT1() asm volatile("cp.async.wait_group 1;" ::: "memory")
#define CP_WAIT0() asm volatile("cp.async.wait_group 0;" ::: "memory")

// ---------------- problem constants ----------------
#define NE 8388608            // 4*2048*1024
#define NS 16777216           // 4*2048*2048
#define WN 1048576            // 1024*1024

static constexpr int BK = 32;
static constexpr int SST  = 40;                     // A tile row stride (half): 80B
static constexpr int SSTB = 136;                    // B-trans tile row stride (half): 272B
static constexpr uint32_t MATB  = 128 * SST * 2;    // 10240: [128 rows][32 k]
static constexpr uint32_t MATBT = 32 * SSTB * 2;    // 8704:  [32 k-rows][128 n]
static constexpr int NSTAGE = 5;

// ---------------- scratch (device globals) ----------------
__device__ __align__(256) __half g_x[3ull * NE];     // fp16 inputs
__device__ __align__(256) __half g_w[3ull * WN];     // W fp16, natural [d][n]
__device__ __align__(256) __half g_qkv[3ull * NE];   // Q/K/V fp16
__device__ __align__(256) float  g_S[NS];
__device__ __align__(256) __half g_ph[NS];           // softmax probs fp16
__device__ __align__(256) float  g_bias[3072];

// ---------------- small kernels ----------------
__global__ void pack_bias(const float* __restrict__ bq, const float* __restrict__ bk,
                          const float* __restrict__ bv, float* __restrict__ dst) {
    int i = blockIdx.x * blockDim.x + threadIdx.x;  // 0..3071
    const float* s = (i < 1024) ? bq : (i < 2048) ? bk : bv;
    dst[i] = s[i & 1023];
}

// fp32 -> fp16, three tensors of `per` elements each (z selects)
__global__ void cvt3(const float* __restrict__ a, const float* __restrict__ b,
                     const float* __restrict__ c, __half* __restrict__ o, size_t per) {
    const int z = blockIdx.z;
    const float* in = (z == 0) ? a : (z == 1) ? b : c;
    size_t li = ((size_t)blockIdx.x * blockDim.x + threadIdx.x) * 4;
    size_t i = (size_t)z * per + li;
    float4 vv = *reinterpret_cast<const float4*>(in + li);
    reinterpret_cast<__half2*>(o + i)[0] = __halves2half2(__float2half(vv.x), __float2half(vv.y));
    reinterpret_cast<__half2*>(o + i)[1] = __halves2half2(__float2half(vv.z), __float2half(vv.w));
}

// row softmax over 2048 -> fp16 probs
__global__ void softmax_h(const float* __restrict__ S, __half* __restrict__ ph) {
    const int row = blockIdx.x;
    const float* x = S + (size_t)row * 2048;
    const int tid = threadIdx.x;  // 256
    float v[8];
    float mx = -1e30f;
#pragma unroll
    for (int i = 0; i < 8; i++) { v[i] = x[tid + i * 256]; mx = fmaxf(mx, v[i]); }
#pragma unroll
    for (int o = 16; o; o >>= 1) mx = fmaxf(mx, __shfl_xor_sync(0xFFFFFFFFu, mx, o));
    __shared__ float redm[8], reds[8];
    if ((tid & 31) == 0) redm[tid >> 5] = mx;
    __syncthreads();
    float m2 = redm[0];
#pragma unroll
    for (int w = 1; w < 8; w++) m2 = fmaxf(m2, redm[w]);
    float s = 0.f;
#pragma unroll
    for (int i = 0; i < 8; i++) { v[i] = __expf(v[i] - m2); s += v[i]; }
#pragma unroll
    for (int o = 16; o; o >>= 1) s += __shfl_xor_sync(0xFFFFFFFFu, s, o);
    if ((tid & 31) == 0) reds[tid >> 5] = s;
    __syncthreads();
    float st = 0.f;
#pragma unroll
    for (int w = 0; w < 8; w++) st += reds[w];
    float inv = 1.f / st;
#pragma unroll
    for (int i = 0; i < 8; i++)
        ph[(size_t)row * 2048 + tid + i * 256] = __float2half(v[i] * inv);
}

// ---------------- HMMA fp16 GEMM: C[128x128]/CTA, 4 warps, 5-stage pipeline ----------------
// TRANSB=0: B K-major [N][K] (ldb = row stride). TRANSB=1: B natural [K][N] (ldb = row stride),
// consumed via ldmatrix.trans.
// MODE 0: outH = fp16(val + bias[z*1024+col]) ; MODE 1: outF = val*scale (fp32).
template <int MODE, int TRANSB>
__global__ void __launch_bounds__(128, 2)
gemm_f16(const __half* __restrict__ A, const __half* __restrict__ B,
         int lda, int ldb, int ldc, int K,
         size_t aBatch, size_t bBatch, size_t cBatch,
         const float* __restrict__ bias, float scale,
         float* __restrict__ outF, __half* __restrict__ outH) {
    constexpr uint32_t BMAT = TRANSB ? MATBT : MATB;
    constexpr uint32_t STAGEB = MATB + BMAT;

    extern __shared__ char sm[];
    const uint32_t sbase = smem_u32(sm);
    const int tid = threadIdx.x;
    const int lane = tid & 31, wid = tid >> 5;
    const int wm = wid >> 1, wn = wid & 1;  // 2x2 warp grid, 64x64 tiles
    const int z = blockIdx.z;
    A += (size_t)z * aBatch;
    B += (size_t)z * bBatch;
    if (MODE == 0) { outH += (size_t)z * cBatch; bias += (size_t)z * 1024; }
    else           { outF += (size_t)z * cBatch; }

    const int mBase = blockIdx.y * 128;
    const int nBase = blockIdx.x * 128;
    const int KT = K / BK;

    auto issue_load = [&](int kb, int stage) {
        const int kOff = kb * BK;
        const uint32_t sb = sbase + (uint32_t)stage * STAGEB;
        // A tile: [128 m-rows][32 k]
#pragma unroll
        for (int i = 0; i < 4; i++) {
            int idx = tid + i * 128;
            int r = idx >> 2, c = idx & 3;
            uint32_t daddr = sb + (uint32_t)(r * SST + c * 8) * 2;
            CP_ASYNC16(daddr, A + (size_t)(mBase + r) * lda + kOff + c * 8);
        }
        if (TRANSB) {
            // B tile: [32 k-rows][128 n]
#pragma unroll
            for (int i = 0; i < 4; i++) {
                int idx = tid + i * 128;
                int r = idx >> 4, c = idx & 15;
                uint32_t daddr = sb + MATB + (uint32_t)(r * SSTB + c * 8) * 2;
                CP_ASYNC16(daddr, B + (size_t)(kOff + r) * ldb + nBase + c * 8);
            }
        } else {
            // B tile: [128 n-rows][32 k]
#pragma unroll
            for (int i = 0; i < 4; i++) {
                int idx = tid + i * 128;
                int r = idx >> 2, c = idx & 3;
                uint32_t daddr = sb + MATB + (uint32_t)(r * SST + c * 8) * 2;
                CP_ASYNC16(daddr, B + (size_t)(nBase + r) * ldb + kOff + c * 8);
            }
        }
        CP_COMMIT();
    };

    float acc[4][8][4];
#pragma unroll
    for (int i = 0; i < 4; i++)
#pragma unroll
        for (int j = 0; j < 8; j++)
#pragma unroll
            for (int e = 0; e < 4; e++) acc[i][j][e] = 0.f;

    // prologue: 4 stages in flight
    issue_load(0, 0);
    issue_load(1, 1);
    issue_load(2, 2);
    issue_load(3, 3);

    int stage = 0, stage4 = 4;
    for (int kb = 0; kb < KT; kb++) {
        if (kb + 3 < KT)      { CP_WAIT3(); }
        else if (kb + 2 < KT) { CP_WAIT2(); }
        else if (kb + 1 < KT) { CP_WAIT1(); }
        else                  { CP_WAIT0(); }
        __syncthreads();
        if (kb + 4 < KT) issue_load(kb + 4, stage4);

        const uint32_t sb = sbase + (uint32_t)stage * STAGEB;
#pragma unroll
        for (int ks = 0; ks < 2; ks++) {
            uint32_t ah[4][4];
            const int rowA = wm * 64 + (lane & 15);
            const int colA = ks * 16 + (lane >> 4) * 8;
#pragma unroll
            for (int mt = 0; mt < 4; mt++) {
                uint32_t off = (uint32_t)((rowA + mt * 16) * SST + colA) * 2;
                ldm_x4(ah[mt], sb + off);
            }
#pragma unroll
            for (int bp = 0; bp < 4; bp++) {
                uint32_t th[4];
                if (TRANSB) {
                    const int kr = ks * 16 + (lane & 7) + (((lane >> 3) & 1) << 3);
                    const int nc = wn * 64 + bp * 16 + ((lane >> 4) << 3);
                    ldm_x4_t(th, sb + MATB + (uint32_t)(kr * SSTB + nc) * 2);
                } else {
                    const int rB = wn * 64 + bp * 16 + ((lane >> 4) << 3) + (lane & 7);
                    const int cB = ks * 16 + (((lane >> 3) & 1) << 3);
                    ldm_x4(th, sb + MATB + (uint32_t)(rB * SST + cB) * 2);
                }
#pragma unroll
                for (int mt = 0; mt < 4; mt++) {
                    mma_f16(acc[mt][bp * 2 + 0], ah[mt], th + 0);
                    mma_f16(acc[mt][bp * 2 + 1], ah[mt], th + 2);
                }
            }
        }
        stage  = (stage  == NSTAGE - 1) ? 0 : stage + 1;
        stage4 = (stage4 == NSTAGE - 1) ? 0 : stage4 + 1;
    }

    // epilogue
    const int g = lane >> 2, tq = lane & 3;
#pragma unroll
    for (int mt = 0; mt < 4; mt++) {
        const int row = mBase + wm * 64 + mt * 16 + g;
#pragma unroll
        for (int nt = 0; nt < 8; nt++) {
            const int col = nBase + wn * 64 + nt * 8 + tq * 2;
            const float* c = acc[mt][nt];
            if (MODE == 0) {
                float b0 = bias[col], b1 = bias[col + 1];
#pragma unroll
                for (int h = 0; h < 2; h++) {
                    size_t o = (size_t)(row + h * 8) * ldc + col;
                    *reinterpret_cast<__half2*>(outH + o) =
                        __halves2half2(__float2half(c[h * 2 + 0] + b0),
                                       __float2half(c[h * 2 + 1] + b1));
                }
            } else {
                float2 v0 = {c[0] * scale, c[1] * scale};
                float2 v1 = {c[2] * scale, c[3] * scale};
                *reinterpret_cast<float2*>(outF + (size_t)row * ldc + col) = v0;
                *reinterpret_cast<float2*>(outF + (size_t)(row + 8) * ldc + col) = v1;
            }
        }
    }
}

// ---------------- launch ----------------
extern "C" void kernel_launch(void* const* d_in, const int* in_sizes, int n_in,
                              void* d_out, int out_size) {
    const float* q_in = (const float*)d_in[0];
    const float* k_in = (const float*)d_in[1];
    const float* v_in = (const float*)d_in[2];
    const float* Wq   = (const float*)d_in[3];
    const float* bq   = (const float*)d_in[4];
    const float* Wk   = (const float*)d_in[5];
    const float* bk   = (const float*)d_in[6];
    const float* Wv   = (const float*)d_in[7];
    const float* bv   = (const float*)d_in[8];
    float* out = (float*)d_out;

    constexpr unsigned SMEM_T = NSTAGE * (MATB + MATBT);  // 94720
    constexpr unsigned SMEM_N = NSTAGE * (MATB + MATB);   // 102400
    cudaFuncSetAttribute((gemm_f16<0, 1>), cudaFuncAttributeMaxDynamicSharedMemorySize, SMEM_T);
    cudaFuncSetAttribute((gemm_f16<1, 0>), cudaFuncAttributeMaxDynamicSharedMemorySize, SMEM_N);
    cudaFuncSetAttribute((gemm_f16<1, 1>), cudaFuncAttributeMaxDynamicSharedMemorySize, SMEM_T);

    void* p;
    cudaGetSymbolAddress(&p, g_x);    __half* x  = (__half*)p;
    cudaGetSymbolAddress(&p, g_w);    __half* w  = (__half*)p;
    cudaGetSymbolAddress(&p, g_qkv);  __half* qkv = (__half*)p;
    cudaGetSymbolAddress(&p, g_S);    float* Sb = (float*)p;
    cudaGetSymbolAddress(&p, g_ph);   __half* ph = (__half*)p;
    cudaGetSymbolAddress(&p, g_bias); float* bias = (float*)p;

    pack_bias<<<12, 256>>>(bq, bk, bv, bias);
    cvt3<<<dim3(8192, 1, 3), 256>>>(q_in, k_in, v_in, x, (size_t)NE);
    cvt3<<<dim3(1024, 1, 3), 256>>>(Wq, Wk, Wv, w, (size_t)WN);
    // all 3 projections (z = q/k/v): [8192,1024] = X x W + b, W natural [d][n] via trans-B
    gemm_f16<0, 1><<<dim3(8, 64, 3), 128, SMEM_T>>>(
        x, w,
        1024, 1024, 1024, 1024,
        (size_t)NE, (size_t)WN, (size_t)NE,
        bias, 0.f, nullptr, qkv);
    // scores: S[2048,2048] = Q x K^T (K-proj is K-major), scale 1/32
    gemm_f16<1, 0><<<dim3(16, 16, 4), 128, SMEM_N>>>(
        qkv, qkv + NE,
        1024, 1024, 2048, 1024,
        (size_t)2048 * 1024, (size_t)2048 * 1024, (size_t)2048 * 2048,
        nullptr, 0.03125f, Sb, nullptr);
    softmax_h<<<8192, 256>>>(Sb, ph);
    // O = P x V, V natural [s][v] via trans-B
    gemm_f16<1, 1><<<dim3(8, 16, 4), 128, SMEM_T>>>(
        ph, qkv + 2ull * NE,
        2048, 1024, 1024, 2048,
        (size_t)2048 * 2048, (size_t)2048 * 1024, (size_t)2048 * 1024,
        nullptr, 1.0f, out, nullptr);
}